// round 15
// baseline (speedup 1.0000x reference)
#include <cuda_runtime.h>
#include <cuda_bf16.h>
#include <cuda_fp16.h>
#include <cstdint>

#define EPS 1e-5f

// ---------------- scratch (static device arrays; allocation-free) ----------
__device__ float g_q[8 * 256 * 768];
__device__ float g_k[8 * 256 * 768];
__device__ float g_v[8 * 256 * 768];
__device__ float g_attn[8 * 256 * 768];
__device__ float g_z[8 * 256 * 768];
__device__ float g_sw[8 * 12 * 256 * 256];            // content scores (+bias)
__device__ __half g_swh[8 * 12 * 256 * 256];          // softmax weights fp16
__device__ __half g_qwh[2048 * 12 * 128];             // q @ Wsk^T fp16
__device__ __half g_pnh[2048ull * 256 * 128];         // LN(paths) fp16
__device__ __nv_bfloat16 g_wt_hi[3072 * 768];         // [Wq|Wk|Wv|Wo]^T bf16 hi
__device__ __nv_bfloat16 g_wt_lo[3072 * 768];         // lo residual

__device__ __forceinline__ uint32_t smem_u32(const void* p) {
    uint32_t a;
    asm("{ .reg .u64 t; cvta.to.shared.u64 t, %1; cvt.u32.u64 %0, t; }"
        : "=r"(a) : "l"(p));
    return a;
}
#define SMEM_SWZ(off) ((off) ^ (((off) >> 3) & 0x70))
__device__ __forceinline__ uint32_t pack2bf(__nv_bfloat16 a, __nv_bfloat16 b) {
    return (uint32_t)__bfloat16_as_ushort(a) | ((uint32_t)__bfloat16_as_ushort(b) << 16);
}
__device__ __forceinline__ void cvt_hilo(float4 v, uint2& hi, uint2& lo) {
    __nv_bfloat16 h0 = __float2bfloat16(v.x), h1 = __float2bfloat16(v.y);
    __nv_bfloat16 h2 = __float2bfloat16(v.z), h3 = __float2bfloat16(v.w);
    __nv_bfloat16 l0 = __float2bfloat16(v.x - __bfloat162float(h0));
    __nv_bfloat16 l1 = __float2bfloat16(v.y - __bfloat162float(h1));
    __nv_bfloat16 l2 = __float2bfloat16(v.z - __bfloat162float(h2));
    __nv_bfloat16 l3 = __float2bfloat16(v.w - __bfloat162float(h3));
    hi = make_uint2(pack2bf(h0, h1), pack2bf(h2, h3));
    lo = make_uint2(pack2bf(l0, l1), pack2bf(l2, l3));
}
__device__ __forceinline__ uint32_t pack2h(__half a, __half b) {
    __half2 t = __halves2half2(a, b);
    return *(uint32_t*)&t;
}

#define LDSM4(r, a) asm volatile( \
    "ldmatrix.sync.aligned.m8n8.x4.shared.b16 {%0,%1,%2,%3}, [%4];" \
    : "=r"((r)[0]), "=r"((r)[1]), "=r"((r)[2]), "=r"((r)[3]) : "r"(a))

#define LDSM2(r, a) asm volatile( \
    "ldmatrix.sync.aligned.m8n8.x2.shared.b16 {%0,%1}, [%2];" \
    : "=r"((r)[0]), "=r"((r)[1]) : "r"(a))

#define LDSM2T(r, a) asm volatile( \
    "ldmatrix.sync.aligned.m8n8.x2.trans.shared.b16 {%0,%1}, [%2];" \
    : "=r"((r)[0]), "=r"((r)[1]) : "r"(a))

#define MMA16816(c, a, b0_, b1_) asm volatile( \
    "mma.sync.aligned.m16n8k16.row.col.f32.bf16.bf16.f32 " \
    "{%0,%1,%2,%3}, {%4,%5,%6,%7}, {%8,%9}, {%0,%1,%2,%3};" \
    : "+f"((c)[0]), "+f"((c)[1]), "+f"((c)[2]), "+f"((c)[3]) \
    : "r"((a)[0]), "r"((a)[1]), "r"((a)[2]), "r"((a)[3]), "r"(b0_), "r"(b1_))

#define MMA16816H(c, a, b0_, b1_) asm volatile( \
    "mma.sync.aligned.m16n8k16.row.col.f32.f16.f16.f32 " \
    "{%0,%1,%2,%3}, {%4,%5,%6,%7}, {%8,%9}, {%0,%1,%2,%3};" \
    : "+f"((c)[0]), "+f"((c)[1]), "+f"((c)[2]), "+f"((c)[3]) \
    : "r"((a)[0]), "r"((a)[1]), "r"((a)[2]), "r"((a)[3]), "r"(b0_), "r"(b1_))

#define CP_ASYNC16(dst, src) asm volatile( \
    "cp.async.cg.shared.global [%0], [%1], 16;" :: "r"(dst), "l"(src) : "memory")
#define CP_COMMIT() asm volatile("cp.async.commit_group;" ::: "memory")
#define CP_WAIT(n) asm volatile("cp.async.wait_group %0;" :: "n"(n) : "memory")

// ===========================================================================
// K0: weight prep — transpose [Wq|Wk|Wv|Wo] into [n][k] bf16 hi/lo.
// ===========================================================================
__global__ __launch_bounds__(256) void prep_weights(
    const float* __restrict__ Wq, const float* __restrict__ Wk,
    const float* __restrict__ Wv, const float* __restrict__ Wo)
{
    __shared__ float s[64][65];
    const int n0 = blockIdx.x * 64;
    const int k0 = blockIdx.y * 64;
    const int tid = threadIdx.x;

    const float* src;
    int c0;
    if (n0 < 768)       { src = Wq; c0 = n0; }
    else if (n0 < 1536) { src = Wk; c0 = n0 - 768; }
    else if (n0 < 2304) { src = Wv; c0 = n0 - 1536; }
    else                { src = Wo; c0 = n0 - 2304; }

    #pragma unroll
    for (int i = 0; i < 4; i++) {
        int fid = i * 256 + tid;
        int kk = fid >> 4, nq = fid & 15;
        float4 v = *(const float4*)(src + (size_t)(k0 + kk) * 768 + c0 + nq * 4);
        s[kk][nq * 4 + 0] = v.x;
        s[kk][nq * 4 + 1] = v.y;
        s[kk][nq * 4 + 2] = v.z;
        s[kk][nq * 4 + 3] = v.w;
    }
    __syncthreads();
    #pragma unroll
    for (int i = 0; i < 4; i++) {
        int fid = i * 256 + tid;
        int nn = fid >> 4, kq = fid & 15;
        float4 v = make_float4(s[kq * 4 + 0][nn], s[kq * 4 + 1][nn],
                               s[kq * 4 + 2][nn], s[kq * 4 + 3][nn]);
        uint2 hi, lo;
        cvt_hilo(v, hi, lo);
        size_t o = (size_t)(n0 + nn) * 768 + k0 + kq * 4;
        *(uint2*)(g_wt_hi + o) = hi;
        *(uint2*)(g_wt_lo + o) = lo;
    }
}

// ===========================================================================
// K_ln: LN(paths) -> g_pnh (fp16). grid 2048, 256 threads; pure streaming.
// ===========================================================================
__global__ __launch_bounds__(256) void ln_paths(
    const float* __restrict__ paths,
    const float* __restrict__ gpath, const float* __restrict__ bpath)
{
    const int bq   = blockIdx.x;
    const int warp = threadIdx.x >> 5;
    const int lane = threadIdx.x & 31;
    const float* prow = paths + (size_t)bq * 32768;
    __half* dst = g_pnh + (size_t)bq * 32768;

    float4 gp = *(const float4*)(gpath + lane * 4);
    float4 bp = *(const float4*)(bpath + lane * 4);

    #pragma unroll
    for (int it = 0; it < 8; it++) {
        const int r0 = it * 32 + warp * 4;
        float4 xv[4];
        #pragma unroll
        for (int j = 0; j < 4; j++)
            xv[j] = *(const float4*)(prow + (size_t)(r0 + j) * 128 + lane * 4);
        #pragma unroll
        for (int j = 0; j < 4; j++) {
            float s  = xv[j].x + xv[j].y + xv[j].z + xv[j].w;
            float sq = xv[j].x * xv[j].x + xv[j].y * xv[j].y +
                       xv[j].z * xv[j].z + xv[j].w * xv[j].w;
            #pragma unroll
            for (int o = 16; o > 0; o >>= 1) {
                s  += __shfl_xor_sync(0xffffffffu, s,  o);
                sq += __shfl_xor_sync(0xffffffffu, sq, o);
            }
            float mu  = s * 0.0078125f;
            float var = sq * 0.0078125f - mu * mu;
            float rs  = rsqrtf(var + EPS);
            float y0 = (xv[j].x - mu) * rs * gp.x + bp.x;
            float y1 = (xv[j].y - mu) * rs * gp.y + bp.y;
            float y2 = (xv[j].z - mu) * rs * gp.z + bp.z;
            float y3 = (xv[j].w - mu) * rs * gp.w + bp.w;
            __half* pr = dst + (size_t)(r0 + j) * 128 + lane * 4;
            *(__half2*)(pr)     = __floats2half2_rn(y0, y1);
            *(__half2*)(pr + 2) = __floats2half2_rn(y2, y3);
        }
    }
}

// ===========================================================================
// K1/K6: HMMA (mma.sync bf16, 3-pass hi/lo split) GEMM for A@W. 2 CTAs/SM.
// ===========================================================================
#define HG_SMEM 65536
__global__ __launch_bounds__(256, 2) void hmma_gemm(
    const float* __restrict__ A, int wt_row0,
    const float* __restrict__ b0, const float* __restrict__ b1,
    const float* __restrict__ b2, int mode)
{
    extern __shared__ char smem[];
    const int tid  = threadIdx.x;
    const int wid  = tid >> 5;
    const int lane = tid & 31;
    const int m0 = blockIdx.y * 128;
    const int n0 = blockIdx.x * 128;
    const int wm = wid & 3;
    const int wn = wid >> 2;

    const uint32_t a_hi = smem_u32(smem);
    const uint32_t a_lo = a_hi + 16384;
    const uint32_t b_hi = a_hi + 32768;
    const uint32_t b_lo = a_hi + 49152;

    const __nv_bfloat16* WTh = g_wt_hi + (size_t)wt_row0 * 768;
    const __nv_bfloat16* WTl = g_wt_lo + (size_t)wt_row0 * 768;

    float acc[2][8][4];
    #pragma unroll
    for (int t = 0; t < 2; t++)
        #pragma unroll
        for (int n = 0; n < 8; n++)
            #pragma unroll
            for (int j = 0; j < 4; j++) acc[t][n][j] = 0.f;

    const int arow = wm * 32 + (lane & 15);
    const int brow = wn * 64 + (lane & 15);
    const int cbyt = (lane >> 4) * 16;

    for (int kc = 0; kc < 12; kc++) {
        #pragma unroll
        for (int i = 0; i < 8; i++) {
            int fid = i * 256 + tid;
            int row = fid >> 4, q = fid & 15;
            float4 v = *(const float4*)(A + (size_t)(m0 + row) * 768 + kc * 64 + q * 4);
            uint2 hi, lo;
            cvt_hilo(v, hi, lo);
            uint32_t off = SMEM_SWZ((uint32_t)(row * 128 + q * 8));
            *(uint2*)(smem + off)         = hi;
            *(uint2*)(smem + 16384 + off) = lo;
        }
        #pragma unroll
        for (int i = 0; i < 4; i++) {
            int fid = i * 256 + tid;
            int row = fid >> 3, q = fid & 7;
            uint4 vh = *(const uint4*)(WTh + (size_t)(n0 + row) * 768 + kc * 64 + q * 8);
            uint4 vl = *(const uint4*)(WTl + (size_t)(n0 + row) * 768 + kc * 64 + q * 8);
            uint32_t off = SMEM_SWZ((uint32_t)(row * 128 + q * 16));
            *(uint4*)(smem + 32768 + off) = vh;
            *(uint4*)(smem + 49152 + off) = vl;
        }
        __syncthreads();

        #pragma unroll
        for (int ks = 0; ks < 4; ks++) {
            const int kb = ks * 32 + cbyt;
            uint32_t ah[2][4], al[2][4];
            #pragma unroll
            for (int t = 0; t < 2; t++) {
                uint32_t off = SMEM_SWZ((uint32_t)((arow + t * 16) * 128 + kb));
                LDSM4(ah[t], a_hi + off);
                LDSM4(al[t], a_lo + off);
            }
            uint32_t bh[4][4], bl[4][4];
            #pragma unroll
            for (int g = 0; g < 4; g++) {
                uint32_t off = SMEM_SWZ((uint32_t)((brow + g * 16) * 128 + kb));
                LDSM4(bh[g], b_hi + off);
                LDSM4(bl[g], b_lo + off);
            }
            #pragma unroll
            for (int t = 0; t < 2; t++)
                #pragma unroll
                for (int g = 0; g < 4; g++) {
                    MMA16816(acc[t][2 * g + 0], ah[t], bh[g][0], bh[g][2]);
                    MMA16816(acc[t][2 * g + 1], ah[t], bh[g][1], bh[g][3]);
                    MMA16816(acc[t][2 * g + 0], ah[t], bl[g][0], bl[g][2]);
                    MMA16816(acc[t][2 * g + 1], ah[t], bl[g][1], bl[g][3]);
                    MMA16816(acc[t][2 * g + 0], al[t], bh[g][0], bh[g][2]);
                    MMA16816(acc[t][2 * g + 1], al[t], bh[g][1], bh[g][3]);
                }
        }
        __syncthreads();
    }

    if (mode == 0) {
        const int wsel = n0 / 768;
        float* dstb = (wsel == 0) ? g_q : (wsel == 1) ? g_k : g_v;
        const float* bias = (wsel == 0) ? b0 : (wsel == 1) ? b1 : b2;
        const float sc = (wsel == 0) ? 0.125f : 1.0f;
        const int clb = n0 - wsel * 768 + wn * 64;
        #pragma unroll
        for (int t = 0; t < 2; t++) {
            int r0 = m0 + wm * 32 + t * 16 + (lane >> 2);
            #pragma unroll
            for (int nt = 0; nt < 8; nt++) {
                int cl = clb + nt * 8 + (lane & 3) * 2;
                float2 bv = *(const float2*)(bias + cl);
                float2 o0, o1;
                o0.x = (acc[t][nt][0] + bv.x) * sc;
                o0.y = (acc[t][nt][1] + bv.y) * sc;
                o1.x = (acc[t][nt][2] + bv.x) * sc;
                o1.y = (acc[t][nt][3] + bv.y) * sc;
                *(float2*)(dstb + (size_t)r0 * 768 + cl)       = o0;
                *(float2*)(dstb + (size_t)(r0 + 8) * 768 + cl) = o1;
            }
        }
    } else {
        const int gcb = n0 + wn * 64;
        #pragma unroll
        for (int t = 0; t < 2; t++) {
            int r0 = m0 + wm * 32 + t * 16 + (lane >> 2);
            #pragma unroll
            for (int nt = 0; nt < 8; nt++) {
                int gc = gcb + nt * 8 + (lane & 3) * 2;
                float2 bv = *(const float2*)(b0 + gc);
                float2 o0, o1;
                o0.x = fmaxf(acc[t][nt][0] + bv.x, 0.f);
                o0.y = fmaxf(acc[t][nt][1] + bv.y, 0.f);
                o1.x = fmaxf(acc[t][nt][2] + bv.x, 0.f);
                o1.y = fmaxf(acc[t][nt][3] + bv.y, 0.f);
                *(float2*)(g_z + (size_t)r0 * 768 + gc)       = o0;
                *(float2*)(g_z + (size_t)(r0 + 8) * 768 + gc) = o1;
            }
        }
    }
}

// ===========================================================================
// K2: qk_hmma — S = Q·K^T + bias, 96 batches, tile 128x128, K=64.
// ===========================================================================
#define QK_SMEM 65536
__global__ __launch_bounds__(256, 2) void qk_hmma(const float* __restrict__ bias)
{
    extern __shared__ char smem[];
    const int tid = threadIdx.x, wid = tid >> 5, lane = tid & 31;
    const int q0 = blockIdx.x * 128, k0 = blockIdx.y * 128;
    const int bh = blockIdx.z, b = bh / 12, h = bh % 12;
    const int wm = wid & 3, wn = wid >> 2;
    const uint32_t a_hi = smem_u32(smem);
    const uint32_t a_lo = a_hi + 16384, b_hi = a_hi + 32768, b_lo = a_hi + 49152;

    const float* Qb = g_q + (size_t)(b * 256 + q0) * 768 + h * 64;
    const float* Kb = g_k + (size_t)(b * 256 + k0) * 768 + h * 64;
    #pragma unroll
    for (int i = 0; i < 8; i++) {
        int fid = i * 256 + tid;
        int row = fid >> 4, c4 = fid & 15;
        uint32_t off = SMEM_SWZ((uint32_t)(row * 128 + c4 * 8));
        uint2 hi, lo;
        cvt_hilo(*(const float4*)(Qb + (size_t)row * 768 + c4 * 4), hi, lo);
        *(uint2*)(smem + off)         = hi;
        *(uint2*)(smem + 16384 + off) = lo;
        cvt_hilo(*(const float4*)(Kb + (size_t)row * 768 + c4 * 4), hi, lo);
        *(uint2*)(smem + 32768 + off) = hi;
        *(uint2*)(smem + 49152 + off) = lo;
    }
    __syncthreads();

    float acc[2][8][4];
    #pragma unroll
    for (int t = 0; t < 2; t++)
        #pragma unroll
        for (int n = 0; n < 8; n++)
            #pragma unroll
            for (int j = 0; j < 4; j++) acc[t][n][j] = 0.f;

    const int arow = wm * 32 + (lane & 15);
    const int brow = wn * 64 + (lane & 15);
    const int cbyt = (lane >> 4) * 16;
    #pragma unroll
    for (int ks = 0; ks < 4; ks++) {
        const int kb = ks * 32 + cbyt;
        uint32_t ah[2][4], al[2][4];
        #pragma unroll
        for (int t = 0; t < 2; t++) {
            uint32_t off = SMEM_SWZ((uint32_t)((arow + t * 16) * 128 + kb));
            LDSM4(ah[t], a_hi + off);
            LDSM4(al[t], a_lo + off);
        }
        uint32_t bhf[4][4], blf[4][4];
        #pragma unroll
        for (int g = 0; g < 4; g++) {
            uint32_t off = SMEM_SWZ((uint32_t)((brow + g * 16) * 128 + kb));
            LDSM4(bhf[g], b_hi + off);
            LDSM4(blf[g], b_lo + off);
        }
        #pragma unroll
        for (int t = 0; t < 2; t++)
            #pragma unroll
            for (int g = 0; g < 4; g++) {
                MMA16816(acc[t][2 * g + 0], ah[t], bhf[g][0], bhf[g][2]);
                MMA16816(acc[t][2 * g + 1], ah[t], bhf[g][1], bhf[g][3]);
                MMA16816(acc[t][2 * g + 0], ah[t], blf[g][0], blf[g][2]);
                MMA16816(acc[t][2 * g + 1], ah[t], blf[g][1], blf[g][3]);
                MMA16816(acc[t][2 * g + 0], al[t], bhf[g][0], bhf[g][2]);
                MMA16816(acc[t][2 * g + 1], al[t], bhf[g][1], bhf[g][3]);
            }
    }

    const size_t rbase = (size_t)bh * 256;
    #pragma unroll
    for (int t = 0; t < 2; t++) {
        int r0 = q0 + wm * 32 + t * 16 + (lane >> 2);
        #pragma unroll
        for (int nt = 0; nt < 8; nt++) {
            int cl = k0 + wn * 64 + nt * 8 + (lane & 3) * 2;
            size_t i0 = (rbase + r0) * 256 + cl;
            size_t i1 = (rbase + r0 + 8) * 256 + cl;
            float2 bv0 = *(const float2*)(bias + i0);
            float2 bv1 = *(const float2*)(bias + i1);
            float2 o0, o1;
            o0.x = acc[t][nt][0] + bv0.x;
            o0.y = acc[t][nt][1] + bv0.y;
            o1.x = acc[t][nt][2] + bv1.x;
            o1.y = acc[t][nt][3] + bv1.y;
            *(float2*)(g_sw + i0) = o0;
            *(float2*)(g_sw + i1) = o1;
        }
    }
}

// ===========================================================================
// K3: qw_hmma — qw[bq, h*128+p] = q[bq,h,:]·Wsk[p,:], fp16 out. grid (16,12).
// ===========================================================================
__global__ __launch_bounds__(256, 2) void qw_hmma(const float* __restrict__ Wsk)
{
    extern __shared__ char smem[];
    const int tid = threadIdx.x, wid = tid >> 5, lane = tid & 31;
    const int m0 = blockIdx.x * 128;
    const int h  = blockIdx.y;
    const int wm = wid & 3, wn = wid >> 2;
    const uint32_t a_hi = smem_u32(smem);
    const uint32_t a_lo = a_hi + 16384, b_hi = a_hi + 32768, b_lo = a_hi + 49152;

    #pragma unroll
    for (int i = 0; i < 8; i++) {
        int fid = i * 256 + tid;
        int row = fid >> 4, c4 = fid & 15;
        uint32_t off = SMEM_SWZ((uint32_t)(row * 128 + c4 * 8));
        uint2 hi, lo;
        cvt_hilo(*(const float4*)(g_q + (size_t)(m0 + row) * 768 + h * 64 + c4 * 4), hi, lo);
        *(uint2*)(smem + off)         = hi;
        *(uint2*)(smem + 16384 + off) = lo;
        cvt_hilo(*(const float4*)(Wsk + row * 64 + c4 * 4), hi, lo);
        *(uint2*)(smem + 32768 + off) = hi;
        *(uint2*)(smem + 49152 + off) = lo;
    }
    __syncthreads();

    float acc[2][8][4];
    #pragma unroll
    for (int t = 0; t < 2; t++)
        #pragma unroll
        for (int n = 0; n < 8; n++)
            #pragma unroll
            for (int j = 0; j < 4; j++) acc[t][n][j] = 0.f;

    const int arow = wm * 32 + (lane & 15);
    const int brow = wn * 64 + (lane & 15);
    const int cbyt = (lane >> 4) * 16;
    #pragma unroll
    for (int ks = 0; ks < 4; ks++) {
        const int kb = ks * 32 + cbyt;
        uint32_t ah[2][4], al[2][4];
        #pragma unroll
        for (int t = 0; t < 2; t++) {
            uint32_t off = SMEM_SWZ((uint32_t)((arow + t * 16) * 128 + kb));
            LDSM4(ah[t], a_hi + off);
            LDSM4(al[t], a_lo + off);
        }
        uint32_t bhf[4][4], blf[4][4];
        #pragma unroll
        for (int g = 0; g < 4; g++) {
            uint32_t off = SMEM_SWZ((uint32_t)((brow + g * 16) * 128 + kb));
            LDSM4(bhf[g], b_hi + off);
            LDSM4(blf[g], b_lo + off);
        }
        #pragma unroll
        for (int t = 0; t < 2; t++)
            #pragma unroll
            for (int g = 0; g < 4; g++) {
                MMA16816(acc[t][2 * g + 0], ah[t], bhf[g][0], bhf[g][2]);
                MMA16816(acc[t][2 * g + 1], ah[t], bhf[g][1], bhf[g][3]);
                MMA16816(acc[t][2 * g + 0], ah[t], blf[g][0], blf[g][2]);
                MMA16816(acc[t][2 * g + 1], ah[t], blf[g][1], blf[g][3]);
                MMA16816(acc[t][2 * g + 0], al[t], bhf[g][0], bhf[g][2]);
                MMA16816(acc[t][2 * g + 1], al[t], bhf[g][1], bhf[g][3]);
            }
    }

    #pragma unroll
    for (int t = 0; t < 2; t++) {
        int r0 = m0 + wm * 32 + t * 16 + (lane >> 2);
        #pragma unroll
        for (int nt = 0; nt < 8; nt++) {
            int cl = h * 128 + wn * 64 + nt * 8 + (lane & 3) * 2;
            *(__half2*)(g_qwh + (size_t)r0 * 1536 + cl) =
                __floats2half2_rn(acc[t][nt][0], acc[t][nt][1]);
            *(__half2*)(g_qwh + (size_t)(r0 + 8) * 1536 + cl) =
                __floats2half2_rn(acc[t][nt][2], acc[t][nt][3]);
        }
    }
}

// ===========================================================================
// K4: attn2 — per (b,q) CTA; pn bulk cp.async from g_pnh; HMMA C, E, F.
// ===========================================================================
#define PN_STR 136
#define QW_STR 136
#define WH_STR 264
#define WSV_STR 136
#define OFF_QWH 69632
#define OFF_WH  73984
#define OFF_SS  82432
#define OFF_QCV 94720
#define OFF_WSV 94784
#define AT_SMEM 112192
__global__ __launch_bounds__(512, 2) void attn_struct_kernel(
    const float* __restrict__ Wsv, const float* __restrict__ bsv,
    const float* __restrict__ bsk)
{
    extern __shared__ char smraw[];
    __half* pn   = (__half*)smraw;
    __half* qwh  = (__half*)(smraw + OFF_QWH);    // A for C; wp fp16 for F
    __half* wh   = (__half*)(smraw + OFF_WH);
    float*  ss   = (float*)(smraw + OFF_SS);
    float*  qcv  = (float*)(smraw + OFF_QCV);
    __half* wsvT = (__half*)(smraw + OFF_WSV);    // [64 d][136 p]
    const uint32_t pn_u   = smem_u32(pn);
    const uint32_t qwh_u  = smem_u32(qwh);
    const uint32_t wh_u   = smem_u32(wh);
    const uint32_t ss_u   = smem_u32(ss);
    const uint32_t wsvT_u = smem_u32(wsvT);

    const int b  = blockIdx.y;
    const int qi = blockIdx.x;
    const int bq = b * 256 + qi;
    const int tid  = threadIdx.x;
    const int warp = tid >> 5;
    const int lane = tid & 31;

    // ---- prologue: bulk cp.async of pn tile (64 KB) + g_sw prefetch ----
    {
        const __half* pnsrc = g_pnh + (size_t)bq * 32768;
        #pragma unroll
        for (int i = 0; i < 8; i++) {
            int idx = i * 512 + tid;          // 0..4095
            int row = idx >> 4, c = idx & 15;
            CP_ASYNC16(pn_u + (uint32_t)(row * (PN_STR * 2) + c * 16),
                       pnsrc + (size_t)row * 128 + c * 8);
        }
        const float* swsrc = g_sw + ((size_t)(b * 12) * 256 + qi) * 256;
        {
            int idx = tid;
            int hh = idx >> 6, k4 = idx & 63;
            CP_ASYNC16(ss_u + (uint32_t)(hh * 256 + k4 * 4) * 4,
                       swsrc + (size_t)hh * 65536 + k4 * 4);
        }
        if (tid < 256) {
            int idx = 512 + tid;
            int hh = idx >> 6, k4 = idx & 63;
            CP_ASYNC16(ss_u + (uint32_t)(hh * 256 + k4 * 4) * 4,
                       swsrc + (size_t)hh * 65536 + k4 * 4);
        }
        CP_COMMIT();
    }

    // ---- overlapped with cp.async: qc, qwh init, pads, WsvT staging ----
    if (warp < 12) {
        const float* qrow = g_q + (size_t)bq * 768 + warp * 64;
        float a = qrow[lane] * bsk[lane] + qrow[lane + 32] * bsk[lane + 32];
        #pragma unroll
        for (int o = 16; o > 0; o >>= 1)
            a += __shfl_xor_sync(0xffffffffu, a, o);
        if (lane == 0) qcv[warp] = a;
    }
    if (tid < 192) {
        uint4 v = *(const uint4*)(g_qwh + (size_t)bq * 1536 + tid * 8);
        int h = (tid * 8) >> 7, p = (tid * 8) & 127;
        *(uint4*)(qwh + h * QW_STR + p) = v;
    } else {
        int t = tid - 192;
        __half2 z = __half2half2(__float2half(0.f));
        if (t < 272) *((__half2*)(qwh + 12 * QW_STR) + t) = z;
        #pragma unroll
        for (int i = 0; i < 2; i++) {
            int o = t + i * 320;
            if (o < 528) *((__half2*)(wh + 12 * WH_STR) + o) = z;
        }
    }
    #pragma unroll
    for (int i = 0; i < 16; i++) {
        int idx = i * 512 + tid;
        int p = idx >> 6, d = idx & 63;
        wsvT[d * WSV_STR + p] = __float2half(Wsv[idx]);
    }

    CP_WAIT(0);
    __syncthreads();

    // ---- Phase C (HMMA): ss[h][key] = qw·pn + qc + prefetched content ----
    {
        const int n0 = warp * 16;
        const uint32_t aaddr = qwh_u + ((lane & 15) * QW_STR + (lane >> 4) * 8) * 2;
        const uint32_t baddr = pn_u + ((n0 + (lane & 15)) * PN_STR + (lane >> 4) * 8) * 2;
        float c0[4] = {0.f, 0.f, 0.f, 0.f};
        float c1[4] = {0.f, 0.f, 0.f, 0.f};
        #pragma unroll
        for (int kc = 0; kc < 8; kc++) {
            uint32_t a[4], bm[4];
            LDSM4(a, aaddr + kc * 32);
            LDSM4(bm, baddr + kc * 32);
            MMA16816H(c0, a, bm[0], bm[2]);
            MMA16816H(c1, a, bm[1], bm[3]);
        }
        const int h0 = lane >> 2;
        const int kk = (lane & 3) * 2;
        {
            float qc0 = qcv[h0];
            float* r = ss + h0 * 256 + n0;
            r[kk]     = c0[0] + qc0 + r[kk];
            r[kk + 1] = c0[1] + qc0 + r[kk + 1];
            r[8 + kk]     = c1[0] + qc0 + r[8 + kk];
            r[8 + kk + 1] = c1[1] + qc0 + r[8 + kk + 1];
        }
        if (h0 < 4) {
            const int h1 = h0 + 8;
            float qc1 = qcv[h1];
            float* r = ss + h1 * 256 + n0;
            r[kk]     = c0[2] + qc1 + r[kk];
            r[kk + 1] = c0[3] + qc1 + r[kk + 1];
            r[8 + kk]     = c1[2] + qc1 + r[8 + kk];
            r[8 + kk + 1] = c1[3] + qc1 + r[8 + kk + 1];
        }
    }
    __syncthreads();

    // ---- Phase D: softmax; fp16 weights -> g_swh and wh ----
    if (warp < 12) {
        float* row = ss + warp * 256;
        float vals[8], m = -1e30f;
        #pragma unroll
        for (int i = 0; i < 8; i++) {
            vals[i] = row[lane + i * 32];
            m = fmaxf(m, vals[i]);
        }
        #pragma unroll
        for (int o = 16; o > 0; o >>= 1)
            m = fmaxf(m, __shfl_xor_sync(0xffffffffu, m, o));
        float s = 0.f;
        #pragma unroll
        for (int i = 0; i < 8; i++) { vals[i] = __expf(vals[i] - m); s += vals[i]; }
        #pragma unroll
        for (int o = 16; o > 0; o >>= 1)
            s += __shfl_xor_sync(0xffffffffu, s, o);
        float inv = 1.f / s;
        __half* gwh = g_swh + ((size_t)(b * 12 + warp) * 256 + qi) * 256;
        __half* whr = wh + warp * WH_STR;
        #pragma unroll
        for (int i = 0; i < 8; i++) {
            __half w = __float2half_rn(vals[i] * inv);
            gwh[lane + i * 32] = w;
            whr[lane + i * 32] = w;
        }
    }
    __syncthreads();

    // ---- Phase E (HMMA): wp[h][p] = Σ_k w[h,k]·pn[k,p] -> qwh (fp16) ----
    {
        const int p0 = warp * 8;
        const uint32_t aaddr = wh_u + ((lane & 15) * WH_STR + (lane >> 4) * 8) * 2;
        const uint32_t baddr = pn_u + ((lane & 15) * PN_STR + p0) * 2;
        float c[4] = {0.f, 0.f, 0.f, 0.f};
        #pragma unroll
        for (int kc = 0; kc < 16; kc++) {
            uint32_t a[4], bm[2];
            LDSM4(a, aaddr + kc * 32);
            LDSM2T(bm, baddr + kc * 16 * PN_STR * 2);
            MMA16816H(c, a, bm[0], bm[1]);
        }
        const int h0 = lane >> 2;
        const int pp = p0 + (lane & 3) * 2;
        *(__half2*)(qwh + h0 * QW_STR + pp) = __floats2half2_rn(c[0], c[1]);
        if (h0 < 4)
            *(__half2*)(qwh + (h0 + 8) * QW_STR + pp) = __floats2half2_rn(c[2], c[3]);
    }
    __syncthreads();

    // ---- Phase F (HMMA, warps 0..7): out[h,d] = Σ_p wp[h,p]·Wsv[p,d]+bsv ----
    if (warp < 8) {
        const int n0 = warp * 8;
        const uint32_t aaddr = qwh_u + ((lane & 15) * QW_STR + (lane >> 4) * 8) * 2;
        const uint32_t baddr = wsvT_u + ((n0 + (lane & 7)) * WSV_STR +
                                         ((lane >> 3) & 1) * 8) * 2;
        float c[4] = {0.f, 0.f, 0.f, 0.f};
        #pragma unroll
        for (int kc = 0; kc < 8; kc++) {
            uint32_t a[4], bm[2];
            LDSM4(a, aaddr + kc * 32);
            LDSM2(bm, baddr + kc * 32);
            MMA16816H(c, a, bm[0], bm[1]);
        }
        float* aout = g_attn + (size_t)bq * 768;
        const int h0 = lane >> 2;
        const int dd = n0 + (lane & 3) * 2;
        float2 bv = *(const float2*)(bsv + dd);
        float2 o0;
        o0.x = c[0] + bv.x;
        o0.y = c[1] + bv.y;
        *(float2*)(aout + h0 * 64 + dd) = o0;
        if (h0 < 4) {
            float2 o1;
            o1.x = c[2] + bv.x;
            o1.y = c[3] + bv.y;
            *(float2*)(aout + (h0 + 8) * 64 + dd) = o1;
        }
    }
}

// ===========================================================================
// K5: wv_hmma — g_attn += W(fp16) @ V(hi/lo fp16). grid (2, 96).
// ===========================================================================
#define WV_SMEM 34816
#define V_STR 72
__global__ __launch_bounds__(256) void wv_hmma()
{
    extern __shared__ char smem[];
    const int tid = threadIdx.x, wid = tid >> 5, lane = tid & 31;
    const int q0 = blockIdx.x * 128;
    const int bh = blockIdx.y, b = bh / 12, h = bh % 12;
    const int wm = wid & 3, wn = wid >> 2;
    const uint32_t w_u = smem_u32(smem);
    const uint32_t vh_u = w_u + 16384;
    const uint32_t vl_u = w_u + 16384 + 9216;

    float acc[2][4][4];
    #pragma unroll
    for (int t = 0; t < 2; t++)
        #pragma unroll
        for (int g = 0; g < 4; g++)
            #pragma unroll
            for (int j = 0; j < 4; j++) acc[t][g][j] = 0.f;

    const __half* Wb = g_swh + ((size_t)bh * 256 + q0) * 256;
    const float* Vb = g_v + (size_t)(b * 256) * 768 + h * 64;

    for (int kc = 0; kc < 4; kc++) {
        #pragma unroll
        for (int i = 0; i < 4; i++) {
            int fid = i * 256 + tid;
            int row = fid >> 3, c8 = fid & 7;
            uint4 v = *(const uint4*)(Wb + (size_t)row * 256 + kc * 64 + c8 * 8);
            *(uint4*)(smem + SMEM_SWZ((uint32_t)(row * 128 + c8 * 16))) = v;
        }
        #pragma unroll
        for (int i = 0; i < 4; i++) {
            int fid = i * 256 + tid;
            int row = fid >> 4, c4 = fid & 15;
            float4 v = *(const float4*)(Vb + (size_t)(kc * 64 + row) * 768 + c4 * 4);
            __half h0 = __float2half(v.x), h1 = __float2half(v.y);
            __half h2 = __float2half(v.z), h3 = __float2half(v.w);
            __half l0 = __float2half(v.x - __half2float(h0));
            __half l1 = __float2half(v.y - __half2float(h1));
            __half l2 = __float2half(v.z - __half2float(h2));
            __half l3 = __float2half(v.w - __half2float(h3));
            uint32_t off = (uint32_t)(row * V_STR + c4 * 4) * 2;
            *(uint2*)(smem + 16384 + off)        = make_uint2(pack2h(h0, h1), pack2h(h2, h3));
            *(uint2*)(smem + 16384 + 9216 + off) = make_uint2(pack2h(l0, l1), pack2h(l2, l3));
        }
        __syncthreads();

        #pragma unroll
        for (int ks = 0; ks < 4; ks++) {
            uint32_t a[2][4];
            #pragma unroll
            for (int t = 0; t < 2; t++) {
                uint32_t off = SMEM_SWZ((uint32_t)((wm * 32 + (lane & 15) + t * 16) * 128 +
                                                   ks * 32 + (lane >> 4) * 16));
                LDSM4(a[t], w_u + off);
            }
            #pragma unroll
            for (int g = 0; g < 4; g++) {
                uint32_t boff = (uint32_t)((ks * 16 + (lane & 15)) * V_STR +
                                           wn * 32 + g * 8) * 2;
                uint32_t bhv[2], blv[2];
                LDSM2T(bhv, vh_u + boff);
                LDSM2T(blv, vl_u + boff);
                #pragma unroll
                for (int t = 0; t < 2; t++) {
                    MMA16816H(acc[t][g], a[t], bhv[0], bhv[1]);
                    MMA16816H(acc[t][g], a[t], blv[0], blv[1]);
                }
            }
        }
        __syncthreads();
    }

    #pragma unroll
    for (int t = 0; t < 2; t++) {
        int r0 = q0 + wm * 32 + t * 16 + (lane >> 2);
        #pragma unroll
        for (int g = 0; g < 4; g++) {
            int col = h * 64 + wn * 32 + g * 8 + (lane & 3) * 2;
            float* d0 = g_attn + ((size_t)(b * 256) + r0) * 768 + col;
            float* d1 = d0 + 8 * 768;
            float2 o0 = *(float2*)d0, o1 = *(float2*)d1;
            o0.x += acc[t][g][0]; o0.y += acc[t][g][1];
            o1.x += acc[t][g][2]; o1.y += acc[t][g][3];
            *(float2*)d0 = o0;
            *(float2*)d1 = o1;
        }
    }
}

// ===========================================================================
// K8: out = LN(nodes + g_z). One warp per row.
// ===========================================================================
__global__ __launch_bounds__(256) void final_ln(
    const float* __restrict__ nodes,
    const float* __restrict__ gout, const float* __restrict__ bout,
    float* __restrict__ out)
{
    const int row  = blockIdx.x * 8 + (threadIdx.x >> 5);
    const int lane = threadIdx.x & 31;
    const float* x1 = nodes + (size_t)row * 768;
    const float* x2 = g_z   + (size_t)row * 768;

    float v[24];
    float s = 0.f, sq = 0.f;
    #pragma unroll
    for (int i = 0; i < 6; i++) {
        float4 a = *(const float4*)(x1 + i * 128 + lane * 4);
        float4 c = *(const float4*)(x2 + i * 128 + lane * 4);
        float t0 = a.x + c.x, t1 = a.y + c.y, t2 = a.z + c.z, t3 = a.w + c.w;
        v[i * 4 + 0] = t0; v[i * 4 + 1] = t1; v[i * 4 + 2] = t2; v[i * 4 + 3] = t3;
        s += t0 + t1 + t2 + t3;
        sq += t0 * t0 + t1 * t1 + t2 * t2 + t3 * t3;
    }
    #pragma unroll
    for (int o = 16; o > 0; o >>= 1) {
        s  += __shfl_xor_sync(0xffffffffu, s,  o);
        sq += __shfl_xor_sync(0xffffffffu, sq, o);
    }
    const float inv = 1.f / 768.f;
    float mu  = s * inv;
    float var = sq * inv - mu * mu;
    float rs  = rsqrtf(var + EPS);

    float* orow = out + (size_t)row * 768;
    #pragma unroll
    for (int i = 0; i < 6; i++) {
        int idx = i * 128 + lane * 4;
        float4 g4 = *(const float4*)(gout + idx);
        float4 b4 = *(const float4*)(bout + idx);
        float4 r;
        r.x = (v[i * 4 + 0] - mu) * rs * g4.x + b4.x;
        r.y = (v[i * 4 + 1] - mu) * rs * g4.y + b4.y;
        r.z = (v[i * 4 + 2] - mu) * rs * g4.z + b4.z;
        r.w = (v[i * 4 + 3] - mu) * rs * g4.w + b4.w;
        *(float4*)(orow + idx) = r;
    }
}

// ===========================================================================
extern "C" void kernel_launch(void* const* d_in, const int* in_sizes, int n_in,
                              void* d_out, int out_size)
{
    const float* nodes = (const float*)d_in[0];
    const float* bias  = (const float*)d_in[1];
    const float* paths = (const float*)d_in[2];
    const float* Wq  = (const float*)d_in[3];
    const float* bq  = (const float*)d_in[4];
    const float* Wk  = (const float*)d_in[5];
    const float* bk  = (const float*)d_in[6];
    const float* Wv  = (const float*)d_in[7];
    const float* bv  = (const float*)d_in[8];
    const float* Wsk = (const float*)d_in[9];
    const float* bsk = (const float*)d_in[10];
    const float* Wsv = (const float*)d_in[11];
    const float* bsv = (const float*)d_in[12];
    const float* Wo  = (const float*)d_in[13];
    const float* bo  = (const float*)d_in[14];
    const float* gpath = (const float*)d_in[15];
    const float* bpath = (const float*)d_in[16];
    const float* gout  = (const float*)d_in[17];
    const float* bout  = (const float*)d_in[18];
    float* out = (float*)d_out;

    static cudaStream_t s2, s3;
    static cudaEvent_t ev_start, ev_qkv, ev_ln, ev_qw;
    static bool init_done = false;
    if (!init_done) {
        cudaFuncSetAttribute(attn_struct_kernel,
                             cudaFuncAttributeMaxDynamicSharedMemorySize, AT_SMEM);
        cudaFuncSetAttribute(hmma_gemm,
                             cudaFuncAttributeMaxDynamicSharedMemorySize, HG_SMEM);
        cudaFuncSetAttribute(qk_hmma,
                             cudaFuncAttributeMaxDynamicSharedMemorySize, QK_SMEM);
        cudaFuncSetAttribute(qw_hmma,
                             cudaFuncAttributeMaxDynamicSharedMemorySize, QK_SMEM);
        cudaStreamCreateWithFlags(&s2, cudaStreamNonBlocking);
        cudaStreamCreateWithFlags(&s3, cudaStreamNonBlocking);
        cudaEventCreateWithFlags(&ev_start, cudaEventDisableTiming);
        cudaEventCreateWithFlags(&ev_qkv, cudaEventDisableTiming);
        cudaEventCreateWithFlags(&ev_ln, cudaEventDisableTiming);
        cudaEventCreateWithFlags(&ev_qw, cudaEventDisableTiming);
        init_done = true;
    }

    float* fa_global;
    cudaGetSymbolAddress((void**)&fa_global, g_attn);

    // fork at start: ln_paths on s2 overlaps with the qkv->scores chain
    cudaEventRecord(ev_start, 0);
    cudaStreamWaitEvent(s2, ev_start, 0);
    ln_paths<<<2048, 256, 0, s2>>>(paths, gpath, bpath);
    cudaEventRecord(ev_ln, s2);

    prep_weights<<<dim3(48, 12), 256>>>(Wq, Wk, Wv, Wo);
    hmma_gemm<<<dim3(18, 16), 256, HG_SMEM>>>(nodes, 0, bq, bk, bv, 0);

    // fork after qkv: qw on s3 overlaps with qk on the default stream
    cudaEventRecord(ev_qkv, 0);
    cudaStreamWaitEvent(s3, ev_qkv, 0);
    qw_hmma<<<dim3(16, 12), 256, QK_SMEM, s3>>>(Wsk);
    cudaEventRecord(ev_qw, s3);

    qk_hmma<<<dim3(2, 2, 96), 256, QK_SMEM>>>(bias);

    // join before attn2
    cudaStreamWaitEvent(0, ev_ln, 0);
    cudaStreamWaitEvent(0, ev_qw, 0);

    attn_struct_kernel<<<dim3(256, 8), 512, AT_SMEM>>>(Wsv, bsv, bsk);
    wv_hmma<<<dim3(2, 96), 256, WV_SMEM>>>();
    hmma_gemm<<<dim3(6, 16), 256, HG_SMEM>>>(fa_global, 2304, bo, bo, bo, 1);
    final_ln<<<256, 256>>>(nodes, gout, bout, out);
}

// round 16
// speedup vs baseline: 1.0875x; 1.0875x over previous
#include <cuda_runtime.h>
#include <cuda_bf16.h>
#include <cuda_fp16.h>
#include <cstdint>

#define EPS 1e-5f

// ---------------- scratch (static device arrays; allocation-free) ----------
__device__ float g_q[8 * 256 * 768];
__device__ float g_k[8 * 256 * 768];
__device__ float g_v[8 * 256 * 768];
__device__ float g_attn[8 * 256 * 768];
__device__ float g_z[8 * 256 * 768];
__device__ float g_sw[8 * 12 * 256 * 256];            // content scores (+bias)
__device__ __half g_swh[8 * 12 * 256 * 256];          // softmax weights fp16
__device__ __half g_qwh[2048 * 12 * 128];             // q @ Wsk^T fp16
__device__ __nv_bfloat16 g_wt_hi[3072 * 768];         // [Wq|Wk|Wv|Wo]^T bf16 hi
__device__ __nv_bfloat16 g_wt_lo[3072 * 768];         // lo residual

__device__ __forceinline__ uint32_t smem_u32(const void* p) {
    uint32_t a;
    asm("{ .reg .u64 t; cvta.to.shared.u64 t, %1; cvt.u32.u64 %0, t; }"
        : "=r"(a) : "l"(p));
    return a;
}
#define SMEM_SWZ(off) ((off) ^ (((off) >> 3) & 0x70))
__device__ __forceinline__ uint32_t pack2bf(__nv_bfloat16 a, __nv_bfloat16 b) {
    return (uint32_t)__bfloat16_as_ushort(a) | ((uint32_t)__bfloat16_as_ushort(b) << 16);
}
__device__ __forceinline__ void cvt_hilo(float4 v, uint2& hi, uint2& lo) {
    __nv_bfloat16 h0 = __float2bfloat16(v.x), h1 = __float2bfloat16(v.y);
    __nv_bfloat16 h2 = __float2bfloat16(v.z), h3 = __float2bfloat16(v.w);
    __nv_bfloat16 l0 = __float2bfloat16(v.x - __bfloat162float(h0));
    __nv_bfloat16 l1 = __float2bfloat16(v.y - __bfloat162float(h1));
    __nv_bfloat16 l2 = __float2bfloat16(v.z - __bfloat162float(h2));
    __nv_bfloat16 l3 = __float2bfloat16(v.w - __bfloat162float(h3));
    hi = make_uint2(pack2bf(h0, h1), pack2bf(h2, h3));
    lo = make_uint2(pack2bf(l0, l1), pack2bf(l2, l3));
}
__device__ __forceinline__ uint32_t pack2h(__half a, __half b) {
    __half2 t = __halves2half2(a, b);
    return *(uint32_t*)&t;
}

#define LDSM4(r, a) asm volatile( \
    "ldmatrix.sync.aligned.m8n8.x4.shared.b16 {%0,%1,%2,%3}, [%4];" \
    : "=r"((r)[0]), "=r"((r)[1]), "=r"((r)[2]), "=r"((r)[3]) : "r"(a))

#define LDSM2(r, a) asm volatile( \
    "ldmatrix.sync.aligned.m8n8.x2.shared.b16 {%0,%1}, [%2];" \
    : "=r"((r)[0]), "=r"((r)[1]) : "r"(a))

#define LDSM2T(r, a) asm volatile( \
    "ldmatrix.sync.aligned.m8n8.x2.trans.shared.b16 {%0,%1}, [%2];" \
    : "=r"((r)[0]), "=r"((r)[1]) : "r"(a))

#define MMA16816(c, a, b0_, b1_) asm volatile( \
    "mma.sync.aligned.m16n8k16.row.col.f32.bf16.bf16.f32 " \
    "{%0,%1,%2,%3}, {%4,%5,%6,%7}, {%8,%9}, {%0,%1,%2,%3};" \
    : "+f"((c)[0]), "+f"((c)[1]), "+f"((c)[2]), "+f"((c)[3]) \
    : "r"((a)[0]), "r"((a)[1]), "r"((a)[2]), "r"((a)[3]), "r"(b0_), "r"(b1_))

#define MMA16816H(c, a, b0_, b1_) asm volatile( \
    "mma.sync.aligned.m16n8k16.row.col.f32.f16.f16.f32 " \
    "{%0,%1,%2,%3}, {%4,%5,%6,%7}, {%8,%9}, {%0,%1,%2,%3};" \
    : "+f"((c)[0]), "+f"((c)[1]), "+f"((c)[2]), "+f"((c)[3]) \
    : "r"((a)[0]), "r"((a)[1]), "r"((a)[2]), "r"((a)[3]), "r"(b0_), "r"(b1_))

#define CP_ASYNC16(dst, src) asm volatile( \
    "cp.async.cg.shared.global [%0], [%1], 16;" :: "r"(dst), "l"(src) : "memory")
#define CP_COMMIT() asm volatile("cp.async.commit_group;" ::: "memory")
#define CP_WAIT(n) asm volatile("cp.async.wait_group %0;" :: "n"(n) : "memory")

// ===========================================================================
// K0: weight prep — transpose [Wq|Wk|Wv|Wo] into [n][k] bf16 hi/lo.
// ===========================================================================
__global__ __launch_bounds__(256) void prep_weights(
    const float* __restrict__ Wq, const float* __restrict__ Wk,
    const float* __restrict__ Wv, const float* __restrict__ Wo)
{
    __shared__ float s[64][65];
    const int n0 = blockIdx.x * 64;
    const int k0 = blockIdx.y * 64;
    const int tid = threadIdx.x;

    const float* src;
    int c0;
    if (n0 < 768)       { src = Wq; c0 = n0; }
    else if (n0 < 1536) { src = Wk; c0 = n0 - 768; }
    else if (n0 < 2304) { src = Wv; c0 = n0 - 1536; }
    else                { src = Wo; c0 = n0 - 2304; }

    #pragma unroll
    for (int i = 0; i < 4; i++) {
        int fid = i * 256 + tid;
        int kk = fid >> 4, nq = fid & 15;
        float4 v = *(const float4*)(src + (size_t)(k0 + kk) * 768 + c0 + nq * 4);
        s[kk][nq * 4 + 0] = v.x;
        s[kk][nq * 4 + 1] = v.y;
        s[kk][nq * 4 + 2] = v.z;
        s[kk][nq * 4 + 3] = v.w;
    }
    __syncthreads();
    #pragma unroll
    for (int i = 0; i < 4; i++) {
        int fid = i * 256 + tid;
        int nn = fid >> 4, kq = fid & 15;
        float4 v = make_float4(s[kq * 4 + 0][nn], s[kq * 4 + 1][nn],
                               s[kq * 4 + 2][nn], s[kq * 4 + 3][nn]);
        uint2 hi, lo;
        cvt_hilo(v, hi, lo);
        size_t o = (size_t)(n0 + nn) * 768 + k0 + kq * 4;
        *(uint2*)(g_wt_hi + o) = hi;
        *(uint2*)(g_wt_lo + o) = lo;
    }
}

// ===========================================================================
// K1/K6: HMMA (mma.sync bf16, 3-pass hi/lo split) GEMM for A@W. 2 CTAs/SM.
// ===========================================================================
#define HG_SMEM 65536
__global__ __launch_bounds__(256, 2) void hmma_gemm(
    const float* __restrict__ A, int wt_row0,
    const float* __restrict__ b0, const float* __restrict__ b1,
    const float* __restrict__ b2, int mode)
{
    extern __shared__ char smem[];
    const int tid  = threadIdx.x;
    const int wid  = tid >> 5;
    const int lane = tid & 31;
    const int m0 = blockIdx.y * 128;
    const int n0 = blockIdx.x * 128;
    const int wm = wid & 3;
    const int wn = wid >> 2;

    const uint32_t a_hi = smem_u32(smem);
    const uint32_t a_lo = a_hi + 16384;
    const uint32_t b_hi = a_hi + 32768;
    const uint32_t b_lo = a_hi + 49152;

    const __nv_bfloat16* WTh = g_wt_hi + (size_t)wt_row0 * 768;
    const __nv_bfloat16* WTl = g_wt_lo + (size_t)wt_row0 * 768;

    float acc[2][8][4];
    #pragma unroll
    for (int t = 0; t < 2; t++)
        #pragma unroll
        for (int n = 0; n < 8; n++)
            #pragma unroll
            for (int j = 0; j < 4; j++) acc[t][n][j] = 0.f;

    const int arow = wm * 32 + (lane & 15);
    const int brow = wn * 64 + (lane & 15);
    const int cbyt = (lane >> 4) * 16;

    for (int kc = 0; kc < 12; kc++) {
        #pragma unroll
        for (int i = 0; i < 8; i++) {
            int fid = i * 256 + tid;
            int row = fid >> 4, q = fid & 15;
            float4 v = *(const float4*)(A + (size_t)(m0 + row) * 768 + kc * 64 + q * 4);
            uint2 hi, lo;
            cvt_hilo(v, hi, lo);
            uint32_t off = SMEM_SWZ((uint32_t)(row * 128 + q * 8));
            *(uint2*)(smem + off)         = hi;
            *(uint2*)(smem + 16384 + off) = lo;
        }
        #pragma unroll
        for (int i = 0; i < 4; i++) {
            int fid = i * 256 + tid;
            int row = fid >> 3, q = fid & 7;
            uint4 vh = *(const uint4*)(WTh + (size_t)(n0 + row) * 768 + kc * 64 + q * 8);
            uint4 vl = *(const uint4*)(WTl + (size_t)(n0 + row) * 768 + kc * 64 + q * 8);
            uint32_t off = SMEM_SWZ((uint32_t)(row * 128 + q * 16));
            *(uint4*)(smem + 32768 + off) = vh;
            *(uint4*)(smem + 49152 + off) = vl;
        }
        __syncthreads();

        #pragma unroll
        for (int ks = 0; ks < 4; ks++) {
            const int kb = ks * 32 + cbyt;
            uint32_t ah[2][4], al[2][4];
            #pragma unroll
            for (int t = 0; t < 2; t++) {
                uint32_t off = SMEM_SWZ((uint32_t)((arow + t * 16) * 128 + kb));
                LDSM4(ah[t], a_hi + off);
                LDSM4(al[t], a_lo + off);
            }
            uint32_t bh[4][4], bl[4][4];
            #pragma unroll
            for (int g = 0; g < 4; g++) {
                uint32_t off = SMEM_SWZ((uint32_t)((brow + g * 16) * 128 + kb));
                LDSM4(bh[g], b_hi + off);
                LDSM4(bl[g], b_lo + off);
            }
            #pragma unroll
            for (int t = 0; t < 2; t++)
                #pragma unroll
                for (int g = 0; g < 4; g++) {
                    MMA16816(acc[t][2 * g + 0], ah[t], bh[g][0], bh[g][2]);
                    MMA16816(acc[t][2 * g + 1], ah[t], bh[g][1], bh[g][3]);
                    MMA16816(acc[t][2 * g + 0], ah[t], bl[g][0], bl[g][2]);
                    MMA16816(acc[t][2 * g + 1], ah[t], bl[g][1], bl[g][3]);
                    MMA16816(acc[t][2 * g + 0], al[t], bh[g][0], bh[g][2]);
                    MMA16816(acc[t][2 * g + 1], al[t], bh[g][1], bh[g][3]);
                }
        }
        __syncthreads();
    }

    if (mode == 0) {
        const int wsel = n0 / 768;
        float* dstb = (wsel == 0) ? g_q : (wsel == 1) ? g_k : g_v;
        const float* bias = (wsel == 0) ? b0 : (wsel == 1) ? b1 : b2;
        const float sc = (wsel == 0) ? 0.125f : 1.0f;
        const int clb = n0 - wsel * 768 + wn * 64;
        #pragma unroll
        for (int t = 0; t < 2; t++) {
            int r0 = m0 + wm * 32 + t * 16 + (lane >> 2);
            #pragma unroll
            for (int nt = 0; nt < 8; nt++) {
                int cl = clb + nt * 8 + (lane & 3) * 2;
                float2 bv = *(const float2*)(bias + cl);
                float2 o0, o1;
                o0.x = (acc[t][nt][0] + bv.x) * sc;
                o0.y = (acc[t][nt][1] + bv.y) * sc;
                o1.x = (acc[t][nt][2] + bv.x) * sc;
                o1.y = (acc[t][nt][3] + bv.y) * sc;
                *(float2*)(dstb + (size_t)r0 * 768 + cl)       = o0;
                *(float2*)(dstb + (size_t)(r0 + 8) * 768 + cl) = o1;
            }
        }
    } else {
        const int gcb = n0 + wn * 64;
        #pragma unroll
        for (int t = 0; t < 2; t++) {
            int r0 = m0 + wm * 32 + t * 16 + (lane >> 2);
            #pragma unroll
            for (int nt = 0; nt < 8; nt++) {
                int gc = gcb + nt * 8 + (lane & 3) * 2;
                float2 bv = *(const float2*)(b0 + gc);
                float2 o0, o1;
                o0.x = fmaxf(acc[t][nt][0] + bv.x, 0.f);
                o0.y = fmaxf(acc[t][nt][1] + bv.y, 0.f);
                o1.x = fmaxf(acc[t][nt][2] + bv.x, 0.f);
                o1.y = fmaxf(acc[t][nt][3] + bv.y, 0.f);
                *(float2*)(g_z + (size_t)r0 * 768 + gc)       = o0;
                *(float2*)(g_z + (size_t)(r0 + 8) * 768 + gc) = o1;
            }
        }
    }
}

// ===========================================================================
// K2: qk_hmma — S = Q·K^T + bias, 96 batches, tile 128x128, K=64.
// ===========================================================================
#define QK_SMEM 65536
__global__ __launch_bounds__(256, 2) void qk_hmma(const float* __restrict__ bias)
{
    extern __shared__ char smem[];
    const int tid = threadIdx.x, wid = tid >> 5, lane = tid & 31;
    const int q0 = blockIdx.x * 128, k0 = blockIdx.y * 128;
    const int bh = blockIdx.z, b = bh / 12, h = bh % 12;
    const int wm = wid & 3, wn = wid >> 2;
    const uint32_t a_hi = smem_u32(smem);
    const uint32_t a_lo = a_hi + 16384, b_hi = a_hi + 32768, b_lo = a_hi + 49152;

    const float* Qb = g_q + (size_t)(b * 256 + q0) * 768 + h * 64;
    const float* Kb = g_k + (size_t)(b * 256 + k0) * 768 + h * 64;
    #pragma unroll
    for (int i = 0; i < 8; i++) {
        int fid = i * 256 + tid;
        int row = fid >> 4, c4 = fid & 15;
        uint32_t off = SMEM_SWZ((uint32_t)(row * 128 + c4 * 8));
        uint2 hi, lo;
        cvt_hilo(*(const float4*)(Qb + (size_t)row * 768 + c4 * 4), hi, lo);
        *(uint2*)(smem + off)         = hi;
        *(uint2*)(smem + 16384 + off) = lo;
        cvt_hilo(*(const float4*)(Kb + (size_t)row * 768 + c4 * 4), hi, lo);
        *(uint2*)(smem + 32768 + off) = hi;
        *(uint2*)(smem + 49152 + off) = lo;
    }
    __syncthreads();

    float acc[2][8][4];
    #pragma unroll
    for (int t = 0; t < 2; t++)
        #pragma unroll
        for (int n = 0; n < 8; n++)
            #pragma unroll
            for (int j = 0; j < 4; j++) acc[t][n][j] = 0.f;

    const int arow = wm * 32 + (lane & 15);
    const int brow = wn * 64 + (lane & 15);
    const int cbyt = (lane >> 4) * 16;
    #pragma unroll
    for (int ks = 0; ks < 4; ks++) {
        const int kb = ks * 32 + cbyt;
        uint32_t ah[2][4], al[2][4];
        #pragma unroll
        for (int t = 0; t < 2; t++) {
            uint32_t off = SMEM_SWZ((uint32_t)((arow + t * 16) * 128 + kb));
            LDSM4(ah[t], a_hi + off);
            LDSM4(al[t], a_lo + off);
        }
        uint32_t bhf[4][4], blf[4][4];
        #pragma unroll
        for (int g = 0; g < 4; g++) {
            uint32_t off = SMEM_SWZ((uint32_t)((brow + g * 16) * 128 + kb));
            LDSM4(bhf[g], b_hi + off);
            LDSM4(blf[g], b_lo + off);
        }
        #pragma unroll
        for (int t = 0; t < 2; t++)
            #pragma unroll
            for (int g = 0; g < 4; g++) {
                MMA16816(acc[t][2 * g + 0], ah[t], bhf[g][0], bhf[g][2]);
                MMA16816(acc[t][2 * g + 1], ah[t], bhf[g][1], bhf[g][3]);
                MMA16816(acc[t][2 * g + 0], ah[t], blf[g][0], blf[g][2]);
                MMA16816(acc[t][2 * g + 1], ah[t], blf[g][1], blf[g][3]);
                MMA16816(acc[t][2 * g + 0], al[t], bhf[g][0], bhf[g][2]);
                MMA16816(acc[t][2 * g + 1], al[t], bhf[g][1], bhf[g][3]);
            }
    }

    const size_t rbase = (size_t)bh * 256;
    #pragma unroll
    for (int t = 0; t < 2; t++) {
        int r0 = q0 + wm * 32 + t * 16 + (lane >> 2);
        #pragma unroll
        for (int nt = 0; nt < 8; nt++) {
            int cl = k0 + wn * 64 + nt * 8 + (lane & 3) * 2;
            size_t i0 = (rbase + r0) * 256 + cl;
            size_t i1 = (rbase + r0 + 8) * 256 + cl;
            float2 bv0 = *(const float2*)(bias + i0);
            float2 bv1 = *(const float2*)(bias + i1);
            float2 o0, o1;
            o0.x = acc[t][nt][0] + bv0.x;
            o0.y = acc[t][nt][1] + bv0.y;
            o1.x = acc[t][nt][2] + bv1.x;
            o1.y = acc[t][nt][3] + bv1.y;
            *(float2*)(g_sw + i0) = o0;
            *(float2*)(g_sw + i1) = o1;
        }
    }
}

// ===========================================================================
// K3: qw_hmma — qw[bq, h*128+p] = q[bq,h,:]·Wsk[p,:], fp16 out. grid (16,12).
// ===========================================================================
__global__ __launch_bounds__(256, 2) void qw_hmma(const float* __restrict__ Wsk)
{
    extern __shared__ char smem[];
    const int tid = threadIdx.x, wid = tid >> 5, lane = tid & 31;
    const int m0 = blockIdx.x * 128;
    const int h  = blockIdx.y;
    const int wm = wid & 3, wn = wid >> 2;
    const uint32_t a_hi = smem_u32(smem);
    const uint32_t a_lo = a_hi + 16384, b_hi = a_hi + 32768, b_lo = a_hi + 49152;

    #pragma unroll
    for (int i = 0; i < 8; i++) {
        int fid = i * 256 + tid;
        int row = fid >> 4, c4 = fid & 15;
        uint32_t off = SMEM_SWZ((uint32_t)(row * 128 + c4 * 8));
        uint2 hi, lo;
        cvt_hilo(*(const float4*)(g_q + (size_t)(m0 + row) * 768 + h * 64 + c4 * 4), hi, lo);
        *(uint2*)(smem + off)         = hi;
        *(uint2*)(smem + 16384 + off) = lo;
        cvt_hilo(*(const float4*)(Wsk + row * 64 + c4 * 4), hi, lo);
        *(uint2*)(smem + 32768 + off) = hi;
        *(uint2*)(smem + 49152 + off) = lo;
    }
    __syncthreads();

    float acc[2][8][4];
    #pragma unroll
    for (int t = 0; t < 2; t++)
        #pragma unroll
        for (int n = 0; n < 8; n++)
            #pragma unroll
            for (int j = 0; j < 4; j++) acc[t][n][j] = 0.f;

    const int arow = wm * 32 + (lane & 15);
    const int brow = wn * 64 + (lane & 15);
    const int cbyt = (lane >> 4) * 16;
    #pragma unroll
    for (int ks = 0; ks < 4; ks++) {
        const int kb = ks * 32 + cbyt;
        uint32_t ah[2][4], al[2][4];
        #pragma unroll
        for (int t = 0; t < 2; t++) {
            uint32_t off = SMEM_SWZ((uint32_t)((arow + t * 16) * 128 + kb));
            LDSM4(ah[t], a_hi + off);
            LDSM4(al[t], a_lo + off);
        }
        uint32_t bhf[4][4], blf[4][4];
        #pragma unroll
        for (int g = 0; g < 4; g++) {
            uint32_t off = SMEM_SWZ((uint32_t)((brow + g * 16) * 128 + kb));
            LDSM4(bhf[g], b_hi + off);
            LDSM4(blf[g], b_lo + off);
        }
        #pragma unroll
        for (int t = 0; t < 2; t++)
            #pragma unroll
            for (int g = 0; g < 4; g++) {
                MMA16816(acc[t][2 * g + 0], ah[t], bhf[g][0], bhf[g][2]);
                MMA16816(acc[t][2 * g + 1], ah[t], bhf[g][1], bhf[g][3]);
                MMA16816(acc[t][2 * g + 0], ah[t], blf[g][0], blf[g][2]);
                MMA16816(acc[t][2 * g + 1], ah[t], blf[g][1], blf[g][3]);
                MMA16816(acc[t][2 * g + 0], al[t], bhf[g][0], bhf[g][2]);
                MMA16816(acc[t][2 * g + 1], al[t], bhf[g][1], bhf[g][3]);
            }
    }

    #pragma unroll
    for (int t = 0; t < 2; t++) {
        int r0 = m0 + wm * 32 + t * 16 + (lane >> 2);
        #pragma unroll
        for (int nt = 0; nt < 8; nt++) {
            int cl = h * 128 + wn * 64 + nt * 8 + (lane & 3) * 2;
            *(__half2*)(g_qwh + (size_t)r0 * 1536 + cl) =
                __floats2half2_rn(acc[t][nt][0], acc[t][nt][1]);
            *(__half2*)(g_qwh + (size_t)(r0 + 8) * 1536 + cl) =
                __floats2half2_rn(acc[t][nt][2], acc[t][nt][3]);
        }
    }
}

// ===========================================================================
// K4: attn_struct — per (b,q) CTA; cp.async LN + g_sw prefetch; qc computed
// in-prologue (warps 0..11); HMMA phases C, E, F (F on warps 0..7).
// ===========================================================================
#define PN_STR 136
#define QW_STR 136
#define WH_STR 264
#define WSV_STR 136
#define STG_STR 132
#define OFF_QWH 69632
#define OFF_WH  73984
#define OFF_SS  82432
#define OFF_QCV 94720
#define OFF_STG 94784
#define AT_SMEM 112192   // 94784 + max(16896 stage, 17408 WsvT)
__global__ __launch_bounds__(512, 2) void attn_struct_kernel(
    const float* __restrict__ paths,
    const float* __restrict__ Wsv, const float* __restrict__ bsv,
    const float* __restrict__ gpath, const float* __restrict__ bpath,
    const float* __restrict__ bsk)
{
    extern __shared__ char smraw[];
    __half* pn   = (__half*)smraw;
    __half* qwh  = (__half*)(smraw + OFF_QWH);    // A for C; wp fp16 for F
    __half* wh   = (__half*)(smraw + OFF_WH);
    float*  ss   = (float*)(smraw + OFF_SS);
    float*  qcv  = (float*)(smraw + OFF_QCV);
    float*  stage = (float*)(smraw + OFF_STG);
    __half* wsvT = (__half*)(smraw + OFF_STG);    // [64 d][136 p] after Phase A
    const uint32_t pn_u   = smem_u32(pn);
    const uint32_t qwh_u  = smem_u32(qwh);
    const uint32_t wh_u   = smem_u32(wh);
    const uint32_t stg_u  = smem_u32(stage);
    const uint32_t ss_u   = smem_u32(ss);
    const uint32_t wsvT_u = stg_u;

    const int b  = blockIdx.y;
    const int qi = blockIdx.x;
    const int bq = b * 256 + qi;
    const int tid  = threadIdx.x;
    const int warp = tid >> 5;
    const int lane = tid & 31;

    // ---- prologue: chunk0 cp.async + g_sw prefetch into ss (group 0) ----
    const float* prow = paths + (size_t)bq * 32768;
    const uint32_t doff = (uint32_t)(warp * STG_STR + lane * 4) * 4;
    {
        CP_ASYNC16(stg_u + doff, prow + (size_t)warp * 128 + lane * 4);
        const float* swsrc = g_sw + ((size_t)(b * 12) * 256 + qi) * 256;
        {
            int idx = tid;
            int hh = idx >> 6, k4 = idx & 63;
            CP_ASYNC16(ss_u + (uint32_t)(hh * 256 + k4 * 4) * 4,
                       swsrc + (size_t)hh * 65536 + k4 * 4);
        }
        if (tid < 256) {
            int idx = 512 + tid;
            int hh = idx >> 6, k4 = idx & 63;
            CP_ASYNC16(ss_u + (uint32_t)(hh * 256 + k4 * 4) * 4,
                       swsrc + (size_t)hh * 65536 + k4 * 4);
        }
        CP_COMMIT();
        CP_ASYNC16(stg_u + 16 * STG_STR * 4 + doff,
                   prow + (size_t)(16 + warp) * 128 + lane * 4);
        CP_COMMIT();
    }

    // ---- qc in-place: warp h computes qcv[h] = q[bq,h,:].bsk (fp32) ----
    if (warp < 12) {
        const float* qrow = g_q + (size_t)bq * 768 + warp * 64;
        float a = qrow[lane] * bsk[lane] + qrow[lane + 32] * bsk[lane + 32];
        #pragma unroll
        for (int o = 16; o > 0; o >>= 1)
            a += __shfl_xor_sync(0xffffffffu, a, o);
        if (lane == 0) qcv[warp] = a;
    }

    // ---- init: qwh from g_qwh, zero pads ----
    if (tid < 192) {
        uint4 v = *(const uint4*)(g_qwh + (size_t)bq * 1536 + tid * 8);
        int h = (tid * 8) >> 7, p = (tid * 8) & 127;
        *(uint4*)(qwh + h * QW_STR + p) = v;
    } else {
        int t = tid - 192;
        __half2 z = __half2half2(__float2half(0.f));
        if (t < 272) *((__half2*)(qwh + 12 * QW_STR) + t) = z;
        #pragma unroll
        for (int i = 0; i < 2; i++) {
            int o = t + i * 320;
            if (o < 528) *((__half2*)(wh + 12 * WH_STR) + o) = z;
        }
    }

    // ---- Phase A: cp.async-pipelined LN (16-row chunks, depth 2) ----
    {
        float4 gp = *(const float4*)(gpath + lane * 4);
        float4 bp = *(const float4*)(bpath + lane * 4);
        for (int c = 0; c < 16; c++) {
            if (c < 15) { CP_WAIT(1); } else { CP_WAIT(0); }
            const float* sp = stage + (c & 1) * (16 * STG_STR) +
                              warp * STG_STR + lane * 4;
            float4 xv = *(const float4*)sp;
            if (c < 14) {
                CP_ASYNC16(stg_u + (c & 1) * (16 * STG_STR * 4) + doff,
                           prow + (size_t)((c + 2) * 16 + warp) * 128 + lane * 4);
                CP_COMMIT();
            }
            float s  = xv.x + xv.y + xv.z + xv.w;
            float sq = xv.x * xv.x + xv.y * xv.y + xv.z * xv.z + xv.w * xv.w;
            #pragma unroll
            for (int o = 16; o > 0; o >>= 1) {
                s  += __shfl_xor_sync(0xffffffffu, s,  o);
                sq += __shfl_xor_sync(0xffffffffu, sq, o);
            }
            float mu  = s * 0.0078125f;
            float var = sq * 0.0078125f - mu * mu;
            float rs  = rsqrtf(var + EPS);
            float y0 = (xv.x - mu) * rs * gp.x + bp.x;
            float y1 = (xv.y - mu) * rs * gp.y + bp.y;
            float y2 = (xv.z - mu) * rs * gp.z + bp.z;
            float y3 = (xv.w - mu) * rs * gp.w + bp.w;
            __half* pr = pn + (c * 16 + warp) * PN_STR + lane * 4;
            *(__half2*)(pr)     = __floats2half2_rn(y0, y1);
            *(__half2*)(pr + 2) = __floats2half2_rn(y2, y3);
        }
    }
    __syncthreads();

    // ---- stage WsvT fp16 into (now dead) stage region: wsvT[d][p] ----
    #pragma unroll
    for (int i = 0; i < 16; i++) {
        int idx = i * 512 + tid;
        int p = idx >> 6, d = idx & 63;
        wsvT[d * WSV_STR + p] = __float2half(Wsv[idx]);
    }

    // ---- Phase C (HMMA): ss[h][key] = qw·pn + qc + prefetched content ----
    {
        const int n0 = warp * 16;
        const uint32_t aaddr = qwh_u + ((lane & 15) * QW_STR + (lane >> 4) * 8) * 2;
        const uint32_t baddr = pn_u + ((n0 + (lane & 15)) * PN_STR + (lane >> 4) * 8) * 2;
        float c0[4] = {0.f, 0.f, 0.f, 0.f};
        float c1[4] = {0.f, 0.f, 0.f, 0.f};
        #pragma unroll
        for (int kc = 0; kc < 8; kc++) {
            uint32_t a[4], bm[4];
            LDSM4(a, aaddr + kc * 32);
            LDSM4(bm, baddr + kc * 32);
            MMA16816H(c0, a, bm[0], bm[2]);
            MMA16816H(c1, a, bm[1], bm[3]);
        }
        const int h0 = lane >> 2;
        const int kk = (lane & 3) * 2;
        {
            float qc0 = qcv[h0];
            float* r = ss + h0 * 256 + n0;
            r[kk]     = c0[0] + qc0 + r[kk];
            r[kk + 1] = c0[1] + qc0 + r[kk + 1];
            r[8 + kk]     = c1[0] + qc0 + r[8 + kk];
            r[8 + kk + 1] = c1[1] + qc0 + r[8 + kk + 1];
        }
        if (h0 < 4) {
            const int h1 = h0 + 8;
            float qc1 = qcv[h1];
            float* r = ss + h1 * 256 + n0;
            r[kk]     = c0[2] + qc1 + r[kk];
            r[kk + 1] = c0[3] + qc1 + r[kk + 1];
            r[8 + kk]     = c1[2] + qc1 + r[8 + kk];
            r[8 + kk + 1] = c1[3] + qc1 + r[8 + kk + 1];
        }
    }
    __syncthreads();

    // ---- Phase D: softmax; fp16 weights -> g_swh and wh ----
    if (warp < 12) {
        float* row = ss + warp * 256;
        float vals[8], m = -1e30f;
        #pragma unroll
        for (int i = 0; i < 8; i++) {
            vals[i] = row[lane + i * 32];
            m = fmaxf(m, vals[i]);
        }
        #pragma unroll
        for (int o = 16; o > 0; o >>= 1)
            m = fmaxf(m, __shfl_xor_sync(0xffffffffu, m, o));
        float s = 0.f;
        #pragma unroll
        for (int i = 0; i < 8; i++) { vals[i] = __expf(vals[i] - m); s += vals[i]; }
        #pragma unroll
        for (int o = 16; o > 0; o >>= 1)
            s += __shfl_xor_sync(0xffffffffu, s, o);
        float inv = 1.f / s;
        __half* gwh = g_swh + ((size_t)(b * 12 + warp) * 256 + qi) * 256;
        __half* whr = wh + warp * WH_STR;
        #pragma unroll
        for (int i = 0; i < 8; i++) {
            __half w = __float2half_rn(vals[i] * inv);
            gwh[lane + i * 32] = w;
            whr[lane + i * 32] = w;
        }
    }
    __syncthreads();

    // ---- Phase E (HMMA): wp[h][p] = Σ_k w[h,k]·pn[k,p] -> qwh (fp16) ----
    {
        const int p0 = warp * 8;
        const uint32_t aaddr = wh_u + ((lane & 15) * WH_STR + (lane >> 4) * 8) * 2;
        const uint32_t baddr = pn_u + ((lane & 15) * PN_STR + p0) * 2;
        float c[4] = {0.f, 0.f, 0.f, 0.f};
        #pragma unroll
        for (int kc = 0; kc < 16; kc++) {
            uint32_t a[4], bm[2];
            LDSM4(a, aaddr + kc * 32);
            LDSM2T(bm, baddr + kc * 16 * PN_STR * 2);
            MMA16816H(c, a, bm[0], bm[1]);
        }
        const int h0 = lane >> 2;
        const int pp = p0 + (lane & 3) * 2;
        *(__half2*)(qwh + h0 * QW_STR + pp) = __floats2half2_rn(c[0], c[1]);
        if (h0 < 4)
            *(__half2*)(qwh + (h0 + 8) * QW_STR + pp) = __floats2half2_rn(c[2], c[3]);
    }
    __syncthreads();

    // ---- Phase F (HMMA, warps 0..7): out[h,d] = Σ_p wp[h,p]·Wsv[p,d]+bsv ----
    if (warp < 8) {
        const int n0 = warp * 8;
        const uint32_t aaddr = qwh_u + ((lane & 15) * QW_STR + (lane >> 4) * 8) * 2;
        const uint32_t baddr = wsvT_u + ((n0 + (lane & 7)) * WSV_STR +
                                         ((lane >> 3) & 1) * 8) * 2;
        float c[4] = {0.f, 0.f, 0.f, 0.f};
        #pragma unroll
        for (int kc = 0; kc < 8; kc++) {
            uint32_t a[4], bm[2];
            LDSM4(a, aaddr + kc * 32);
            LDSM2(bm, baddr + kc * 32);
            MMA16816H(c, a, bm[0], bm[1]);
        }
        float* aout = g_attn + (size_t)bq * 768;
        const int h0 = lane >> 2;
        const int dd = n0 + (lane & 3) * 2;
        float2 bv = *(const float2*)(bsv + dd);
        float2 o0;
        o0.x = c[0] + bv.x;
        o0.y = c[1] + bv.y;
        *(float2*)(aout + h0 * 64 + dd) = o0;
        if (h0 < 4) {
            float2 o1;
            o1.x = c[2] + bv.x;
            o1.y = c[3] + bv.y;
            *(float2*)(aout + (h0 + 8) * 64 + dd) = o1;
        }
    }
}

// ===========================================================================
// K5: wv_hmma — g_attn += W(fp16) @ V(hi/lo fp16). grid (2, 96). 2 CTAs/SM.
// ===========================================================================
#define WV_SMEM 34816
#define V_STR 72
__global__ __launch_bounds__(256, 2) void wv_hmma()
{
    extern __shared__ char smem[];
    const int tid = threadIdx.x, wid = tid >> 5, lane = tid & 31;
    const int q0 = blockIdx.x * 128;
    const int bh = blockIdx.y, b = bh / 12, h = bh % 12;
    const int wm = wid & 3, wn = wid >> 2;
    const uint32_t w_u = smem_u32(smem);
    const uint32_t vh_u = w_u + 16384;
    const uint32_t vl_u = w_u + 16384 + 9216;

    float acc[2][4][4];
    #pragma unroll
    for (int t = 0; t < 2; t++)
        #pragma unroll
        for (int g = 0; g < 4; g++)
            #pragma unroll
            for (int j = 0; j < 4; j++) acc[t][g][j] = 0.f;

    const __half* Wb = g_swh + ((size_t)bh * 256 + q0) * 256;
    const float* Vb = g_v + (size_t)(b * 256) * 768 + h * 64;

    for (int kc = 0; kc < 4; kc++) {
        #pragma unroll
        for (int i = 0; i < 4; i++) {
            int fid = i * 256 + tid;
            int row = fid >> 3, c8 = fid & 7;
            uint4 v = *(const uint4*)(Wb + (size_t)row * 256 + kc * 64 + c8 * 8);
            *(uint4*)(smem + SMEM_SWZ((uint32_t)(row * 128 + c8 * 16))) = v;
        }
        #pragma unroll
        for (int i = 0; i < 4; i++) {
            int fid = i * 256 + tid;
            int row = fid >> 4, c4 = fid & 15;
            float4 v = *(const float4*)(Vb + (size_t)(kc * 64 + row) * 768 + c4 * 4);
            __half h0 = __float2half(v.x), h1 = __float2half(v.y);
            __half h2 = __float2half(v.z), h3 = __float2half(v.w);
            __half l0 = __float2half(v.x - __half2float(h0));
            __half l1 = __float2half(v.y - __half2float(h1));
            __half l2 = __float2half(v.z - __half2float(h2));
            __half l3 = __float2half(v.w - __half2float(h3));
            uint32_t off = (uint32_t)(row * V_STR + c4 * 4) * 2;
            *(uint2*)(smem + 16384 + off)        = make_uint2(pack2h(h0, h1), pack2h(h2, h3));
            *(uint2*)(smem + 16384 + 9216 + off) = make_uint2(pack2h(l0, l1), pack2h(l2, l3));
        }
        __syncthreads();

        #pragma unroll
        for (int ks = 0; ks < 4; ks++) {
            uint32_t a[2][4];
            #pragma unroll
            for (int t = 0; t < 2; t++) {
                uint32_t off = SMEM_SWZ((uint32_t)((wm * 32 + (lane & 15) + t * 16) * 128 +
                                                   ks * 32 + (lane >> 4) * 16));
                LDSM4(a[t], w_u + off);
            }
            #pragma unroll
            for (int g = 0; g < 4; g++) {
                uint32_t boff = (uint32_t)((ks * 16 + (lane & 15)) * V_STR +
                                           wn * 32 + g * 8) * 2;
                uint32_t bhv[2], blv[2];
                LDSM2T(bhv, vh_u + boff);
                LDSM2T(blv, vl_u + boff);
                #pragma unroll
                for (int t = 0; t < 2; t++) {
                    MMA16816H(acc[t][g], a[t], bhv[0], bhv[1]);
                    MMA16816H(acc[t][g], a[t], blv[0], blv[1]);
                }
            }
        }
        __syncthreads();
    }

    #pragma unroll
    for (int t = 0; t < 2; t++) {
        int r0 = q0 + wm * 32 + t * 16 + (lane >> 2);
        #pragma unroll
        for (int g = 0; g < 4; g++) {
            int col = h * 64 + wn * 32 + g * 8 + (lane & 3) * 2;
            float* d0 = g_attn + ((size_t)(b * 256) + r0) * 768 + col;
            float* d1 = d0 + 8 * 768;
            float2 o0 = *(float2*)d0, o1 = *(float2*)d1;
            o0.x += acc[t][g][0]; o0.y += acc[t][g][1];
            o1.x += acc[t][g][2]; o1.y += acc[t][g][3];
            *(float2*)d0 = o0;
            *(float2*)d1 = o1;
        }
    }
}

// ===========================================================================
// K8: out = LN(nodes + g_z). One warp per row.
// ===========================================================================
__global__ __launch_bounds__(256) void final_ln(
    const float* __restrict__ nodes,
    const float* __restrict__ gout, const float* __restrict__ bout,
    float* __restrict__ out)
{
    const int row  = blockIdx.x * 8 + (threadIdx.x >> 5);
    const int lane = threadIdx.x & 31;
    const float* x1 = nodes + (size_t)row * 768;
    const float* x2 = g_z   + (size_t)row * 768;

    float v[24];
    float s = 0.f, sq = 0.f;
    #pragma unroll
    for (int i = 0; i < 6; i++) {
        float4 a = *(const float4*)(x1 + i * 128 + lane * 4);
        float4 c = *(const float4*)(x2 + i * 128 + lane * 4);
        float t0 = a.x + c.x, t1 = a.y + c.y, t2 = a.z + c.z, t3 = a.w + c.w;
        v[i * 4 + 0] = t0; v[i * 4 + 1] = t1; v[i * 4 + 2] = t2; v[i * 4 + 3] = t3;
        s += t0 + t1 + t2 + t3;
        sq += t0 * t0 + t1 * t1 + t2 * t2 + t3 * t3;
    }
    #pragma unroll
    for (int o = 16; o > 0; o >>= 1) {
        s  += __shfl_xor_sync(0xffffffffu, s,  o);
        sq += __shfl_xor_sync(0xffffffffu, sq, o);
    }
    const float inv = 1.f / 768.f;
    float mu  = s * inv;
    float var = sq * inv - mu * mu;
    float rs  = rsqrtf(var + EPS);

    float* orow = out + (size_t)row * 768;
    #pragma unroll
    for (int i = 0; i < 6; i++) {
        int idx = i * 128 + lane * 4;
        float4 g4 = *(const float4*)(gout + idx);
        float4 b4 = *(const float4*)(bout + idx);
        float4 r;
        r.x = (v[i * 4 + 0] - mu) * rs * g4.x + b4.x;
        r.y = (v[i * 4 + 1] - mu) * rs * g4.y + b4.y;
        r.z = (v[i * 4 + 2] - mu) * rs * g4.z + b4.z;
        r.w = (v[i * 4 + 3] - mu) * rs * g4.w + b4.w;
        *(float4*)(orow + idx) = r;
    }
}

// ===========================================================================
extern "C" void kernel_launch(void* const* d_in, const int* in_sizes, int n_in,
                              void* d_out, int out_size)
{
    const float* nodes = (const float*)d_in[0];
    const float* bias  = (const float*)d_in[1];
    const float* paths = (const float*)d_in[2];
    const float* Wq  = (const float*)d_in[3];
    const float* bq  = (const float*)d_in[4];
    const float* Wk  = (const float*)d_in[5];
    const float* bk  = (const float*)d_in[6];
    const float* Wv  = (const float*)d_in[7];
    const float* bv  = (const float*)d_in[8];
    const float* Wsk = (const float*)d_in[9];
    const float* bsk = (const float*)d_in[10];
    const float* Wsv = (const float*)d_in[11];
    const float* bsv = (const float*)d_in[12];
    const float* Wo  = (const float*)d_in[13];
    const float* bo  = (const float*)d_in[14];
    const float* gpath = (const float*)d_in[15];
    const float* bpath = (const float*)d_in[16];
    const float* gout  = (const float*)d_in[17];
    const float* bout  = (const float*)d_in[18];
    float* out = (float*)d_out;

    static cudaStream_t s2;
    static cudaEvent_t ev_fork, ev_join;
    static bool init_done = false;
    if (!init_done) {
        cudaFuncSetAttribute(attn_struct_kernel,
                             cudaFuncAttributeMaxDynamicSharedMemorySize, AT_SMEM);
        cudaFuncSetAttribute(hmma_gemm,
                             cudaFuncAttributeMaxDynamicSharedMemorySize, HG_SMEM);
        cudaFuncSetAttribute(qk_hmma,
                             cudaFuncAttributeMaxDynamicSharedMemorySize, QK_SMEM);
        cudaFuncSetAttribute(qw_hmma,
                             cudaFuncAttributeMaxDynamicSharedMemorySize, QK_SMEM);
        cudaStreamCreateWithFlags(&s2, cudaStreamNonBlocking);
        cudaEventCreateWithFlags(&ev_fork, cudaEventDisableTiming);
        cudaEventCreateWithFlags(&ev_join, cudaEventDisableTiming);
        init_done = true;
    }

    float* fa_global;
    cudaGetSymbolAddress((void**)&fa_global, g_attn);

    prep_weights<<<dim3(48, 12), 256>>>(Wq, Wk, Wv, Wo);
    hmma_gemm<<<dim3(18, 16), 256, HG_SMEM>>>(nodes, 0, bq, bk, bv, 0);

    // fork: qw on s2 runs concurrently with qk on the default stream
    cudaEventRecord(ev_fork, 0);
    cudaStreamWaitEvent(s2, ev_fork, 0);
    qw_hmma<<<dim3(16, 12), 256, QK_SMEM, s2>>>(Wsk);
    qk_hmma<<<dim3(2, 2, 96), 256, QK_SMEM>>>(bias);
    cudaEventRecord(ev_join, s2);
    cudaStreamWaitEvent(0, ev_join, 0);

    attn_struct_kernel<<<dim3(256, 8), 512, AT_SMEM>>>(
        paths, Wsv, bsv, gpath, bpath, bsk);
    wv_hmma<<<dim3(2, 96), 256, WV_SMEM>>>();
    hmma_gemm<<<dim3(6, 16), 256, HG_SMEM>>>(fa_global, 2304, bo, bo, bo, 1);
    final_ln<<<256, 256>>>(nodes, gout, bout, out);
}

// round 17
// speedup vs baseline: 1.0974x; 1.0091x over previous
#include <cuda_runtime.h>
#include <cuda_bf16.h>
#include <cuda_fp16.h>
#include <cstdint>

#define EPS 1e-5f

// ---------------- scratch (static device arrays; allocation-free) ----------
__device__ float g_q[8 * 256 * 768];
__device__ float g_k[8 * 256 * 768];
__device__ float g_v[8 * 256 * 768];
__device__ float g_attn[8 * 256 * 768];
__device__ float g_z[8 * 256 * 768];
__device__ float g_sw[8 * 12 * 256 * 256];            // content scores (+bias)
__device__ __half g_swh[8 * 12 * 256 * 256];          // softmax weights fp16
__device__ __half g_qwh[2048 * 12 * 128];             // q @ Wsk^T fp16
__device__ __nv_bfloat16 g_act_hi[2048 * 768];        // activation bf16 hi
__device__ __nv_bfloat16 g_act_lo[2048 * 768];        // activation bf16 lo
__device__ __nv_bfloat16 g_wt_hi[3072 * 768];         // [Wq|Wk|Wv|Wo]^T bf16 hi
__device__ __nv_bfloat16 g_wt_lo[3072 * 768];         // lo residual

__device__ __forceinline__ uint32_t smem_u32(const void* p) {
    uint32_t a;
    asm("{ .reg .u64 t; cvta.to.shared.u64 t, %1; cvt.u32.u64 %0, t; }"
        : "=r"(a) : "l"(p));
    return a;
}
#define SMEM_SWZ(off) ((off) ^ (((off) >> 3) & 0x70))
__device__ __forceinline__ uint32_t pack2bf(__nv_bfloat16 a, __nv_bfloat16 b) {
    return (uint32_t)__bfloat16_as_ushort(a) | ((uint32_t)__bfloat16_as_ushort(b) << 16);
}
__device__ __forceinline__ void cvt_hilo(float4 v, uint2& hi, uint2& lo) {
    __nv_bfloat16 h0 = __float2bfloat16(v.x), h1 = __float2bfloat16(v.y);
    __nv_bfloat16 h2 = __float2bfloat16(v.z), h3 = __float2bfloat16(v.w);
    __nv_bfloat16 l0 = __float2bfloat16(v.x - __bfloat162float(h0));
    __nv_bfloat16 l1 = __float2bfloat16(v.y - __bfloat162float(h1));
    __nv_bfloat16 l2 = __float2bfloat16(v.z - __bfloat162float(h2));
    __nv_bfloat16 l3 = __float2bfloat16(v.w - __bfloat162float(h3));
    hi = make_uint2(pack2bf(h0, h1), pack2bf(h2, h3));
    lo = make_uint2(pack2bf(l0, l1), pack2bf(l2, l3));
}
__device__ __forceinline__ uint32_t pack2h(__half a, __half b) {
    __half2 t = __halves2half2(a, b);
    return *(uint32_t*)&t;
}

#define LDSM4(r, a) asm volatile( \
    "ldmatrix.sync.aligned.m8n8.x4.shared.b16 {%0,%1,%2,%3}, [%4];" \
    : "=r"((r)[0]), "=r"((r)[1]), "=r"((r)[2]), "=r"((r)[3]) : "r"(a))

#define LDSM2(r, a) asm volatile( \
    "ldmatrix.sync.aligned.m8n8.x2.shared.b16 {%0,%1}, [%2];" \
    : "=r"((r)[0]), "=r"((r)[1]) : "r"(a))

#define LDSM2T(r, a) asm volatile( \
    "ldmatrix.sync.aligned.m8n8.x2.trans.shared.b16 {%0,%1}, [%2];" \
    : "=r"((r)[0]), "=r"((r)[1]) : "r"(a))

#define MMA16816(c, a, b0_, b1_) asm volatile( \
    "mma.sync.aligned.m16n8k16.row.col.f32.bf16.bf16.f32 " \
    "{%0,%1,%2,%3}, {%4,%5,%6,%7}, {%8,%9}, {%0,%1,%2,%3};" \
    : "+f"((c)[0]), "+f"((c)[1]), "+f"((c)[2]), "+f"((c)[3]) \
    : "r"((a)[0]), "r"((a)[1]), "r"((a)[2]), "r"((a)[3]), "r"(b0_), "r"(b1_))

#define MMA16816H(c, a, b0_, b1_) asm volatile( \
    "mma.sync.aligned.m16n8k16.row.col.f32.f16.f16.f32 " \
    "{%0,%1,%2,%3}, {%4,%5,%6,%7}, {%8,%9}, {%0,%1,%2,%3};" \
    : "+f"((c)[0]), "+f"((c)[1]), "+f"((c)[2]), "+f"((c)[3]) \
    : "r"((a)[0]), "r"((a)[1]), "r"((a)[2]), "r"((a)[3]), "r"(b0_), "r"(b1_))

#define CP_ASYNC16(dst, src) asm volatile( \
    "cp.async.cg.shared.global [%0], [%1], 16;" :: "r"(dst), "l"(src) : "memory")
#define CP_COMMIT() asm volatile("cp.async.commit_group;" ::: "memory")
#define CP_WAIT(n) asm volatile("cp.async.wait_group %0;" :: "n"(n) : "memory")

// ===========================================================================
// K0: weight prep — transpose [Wq|Wk|Wv|Wo] into [n][k] bf16 hi/lo.
// ===========================================================================
__global__ __launch_bounds__(256) void prep_weights(
    const float* __restrict__ Wq, const float* __restrict__ Wk,
    const float* __restrict__ Wv, const float* __restrict__ Wo)
{
    __shared__ float s[64][65];
    const int n0 = blockIdx.x * 64;
    const int k0 = blockIdx.y * 64;
    const int tid = threadIdx.x;

    const float* src;
    int c0;
    if (n0 < 768)       { src = Wq; c0 = n0; }
    else if (n0 < 1536) { src = Wk; c0 = n0 - 768; }
    else if (n0 < 2304) { src = Wv; c0 = n0 - 1536; }
    else                { src = Wo; c0 = n0 - 2304; }

    #pragma unroll
    for (int i = 0; i < 4; i++) {
        int fid = i * 256 + tid;
        int kk = fid >> 4, nq = fid & 15;
        float4 v = *(const float4*)(src + (size_t)(k0 + kk) * 768 + c0 + nq * 4);
        s[kk][nq * 4 + 0] = v.x;
        s[kk][nq * 4 + 1] = v.y;
        s[kk][nq * 4 + 2] = v.z;
        s[kk][nq * 4 + 3] = v.w;
    }
    __syncthreads();
    #pragma unroll
    for (int i = 0; i < 4; i++) {
        int fid = i * 256 + tid;
        int nn = fid >> 4, kq = fid & 15;
        float4 v = make_float4(s[kq * 4 + 0][nn], s[kq * 4 + 1][nn],
                               s[kq * 4 + 2][nn], s[kq * 4 + 3][nn]);
        uint2 hi, lo;
        cvt_hilo(v, hi, lo);
        size_t o = (size_t)(n0 + nn) * 768 + k0 + kq * 4;
        *(uint2*)(g_wt_hi + o) = hi;
        *(uint2*)(g_wt_lo + o) = lo;
    }
}

// ===========================================================================
// K0b: prep_act — elementwise fp32 -> bf16 hi/lo split of an activation
// matrix [2048 x 768]. grid 768, 256 threads, 8 elems/thread.
// ===========================================================================
__global__ __launch_bounds__(256) void prep_act(const float* __restrict__ src)
{
    size_t idx = ((size_t)blockIdx.x * 256 + threadIdx.x) * 8;
    float4 v0 = *(const float4*)(src + idx);
    float4 v1 = *(const float4*)(src + idx + 4);
    uint2 h, l;
    cvt_hilo(v0, h, l);
    *(uint2*)(g_act_hi + idx) = h;
    *(uint2*)(g_act_lo + idx) = l;
    cvt_hilo(v1, h, l);
    *(uint2*)(g_act_hi + idx + 4) = h;
    *(uint2*)(g_act_lo + idx + 4) = l;
}

// ===========================================================================
// K1/K7: HMMA (mma.sync bf16, 3-pass hi/lo split) GEMM for A@W. 2 CTAs/SM.
// A is pre-converted bf16 hi/lo in g_act_hi/lo.
// ===========================================================================
#define HG_SMEM 65536
__global__ __launch_bounds__(256, 2) void hmma_gemm(
    int wt_row0,
    const float* __restrict__ b0, const float* __restrict__ b1,
    const float* __restrict__ b2, int mode)
{
    extern __shared__ char smem[];
    const int tid  = threadIdx.x;
    const int wid  = tid >> 5;
    const int lane = tid & 31;
    const int m0 = blockIdx.y * 128;
    const int n0 = blockIdx.x * 128;
    const int wm = wid & 3;
    const int wn = wid >> 2;

    const uint32_t a_hi = smem_u32(smem);
    const uint32_t a_lo = a_hi + 16384;
    const uint32_t b_hi = a_hi + 32768;
    const uint32_t b_lo = a_hi + 49152;

    const __nv_bfloat16* WTh = g_wt_hi + (size_t)wt_row0 * 768;
    const __nv_bfloat16* WTl = g_wt_lo + (size_t)wt_row0 * 768;

    float acc[2][8][4];
    #pragma unroll
    for (int t = 0; t < 2; t++)
        #pragma unroll
        for (int n = 0; n < 8; n++)
            #pragma unroll
            for (int j = 0; j < 4; j++) acc[t][n][j] = 0.f;

    const int arow = wm * 32 + (lane & 15);
    const int brow = wn * 64 + (lane & 15);
    const int cbyt = (lane >> 4) * 16;

    for (int kc = 0; kc < 12; kc++) {
        #pragma unroll
        for (int i = 0; i < 4; i++) {
            int fid = i * 256 + tid;
            int row = fid >> 3, q = fid & 7;
            uint4 vh = *(const uint4*)(g_act_hi + (size_t)(m0 + row) * 768 + kc * 64 + q * 8);
            uint4 vl = *(const uint4*)(g_act_lo + (size_t)(m0 + row) * 768 + kc * 64 + q * 8);
            uint32_t off = SMEM_SWZ((uint32_t)(row * 128 + q * 16));
            *(uint4*)(smem + off)         = vh;
            *(uint4*)(smem + 16384 + off) = vl;
        }
        #pragma unroll
        for (int i = 0; i < 4; i++) {
            int fid = i * 256 + tid;
            int row = fid >> 3, q = fid & 7;
            uint4 vh = *(const uint4*)(WTh + (size_t)(n0 + row) * 768 + kc * 64 + q * 8);
            uint4 vl = *(const uint4*)(WTl + (size_t)(n0 + row) * 768 + kc * 64 + q * 8);
            uint32_t off = SMEM_SWZ((uint32_t)(row * 128 + q * 16));
            *(uint4*)(smem + 32768 + off) = vh;
            *(uint4*)(smem + 49152 + off) = vl;
        }
        __syncthreads();

        #pragma unroll
        for (int ks = 0; ks < 4; ks++) {
            const int kb = ks * 32 + cbyt;
            uint32_t ah[2][4], al[2][4];
            #pragma unroll
            for (int t = 0; t < 2; t++) {
                uint32_t off = SMEM_SWZ((uint32_t)((arow + t * 16) * 128 + kb));
                LDSM4(ah[t], a_hi + off);
                LDSM4(al[t], a_lo + off);
            }
            uint32_t bh[4][4], bl[4][4];
            #pragma unroll
            for (int g = 0; g < 4; g++) {
                uint32_t off = SMEM_SWZ((uint32_t)((brow + g * 16) * 128 + kb));
                LDSM4(bh[g], b_hi + off);
                LDSM4(bl[g], b_lo + off);
            }
            #pragma unroll
            for (int t = 0; t < 2; t++)
                #pragma unroll
                for (int g = 0; g < 4; g++) {
                    MMA16816(acc[t][2 * g + 0], ah[t], bh[g][0], bh[g][2]);
                    MMA16816(acc[t][2 * g + 1], ah[t], bh[g][1], bh[g][3]);
                    MMA16816(acc[t][2 * g + 0], ah[t], bl[g][0], bl[g][2]);
                    MMA16816(acc[t][2 * g + 1], ah[t], bl[g][1], bl[g][3]);
                    MMA16816(acc[t][2 * g + 0], al[t], bh[g][0], bh[g][2]);
                    MMA16816(acc[t][2 * g + 1], al[t], bh[g][1], bh[g][3]);
                }
        }
        __syncthreads();
    }

    if (mode == 0) {
        const int wsel = n0 / 768;
        float* dstb = (wsel == 0) ? g_q : (wsel == 1) ? g_k : g_v;
        const float* bias = (wsel == 0) ? b0 : (wsel == 1) ? b1 : b2;
        const float sc = (wsel == 0) ? 0.125f : 1.0f;
        const int clb = n0 - wsel * 768 + wn * 64;
        #pragma unroll
        for (int t = 0; t < 2; t++) {
            int r0 = m0 + wm * 32 + t * 16 + (lane >> 2);
            #pragma unroll
            for (int nt = 0; nt < 8; nt++) {
                int cl = clb + nt * 8 + (lane & 3) * 2;
                float2 bv = *(const float2*)(bias + cl);
                float2 o0, o1;
                o0.x = (acc[t][nt][0] + bv.x) * sc;
                o0.y = (acc[t][nt][1] + bv.y) * sc;
                o1.x = (acc[t][nt][2] + bv.x) * sc;
                o1.y = (acc[t][nt][3] + bv.y) * sc;
                *(float2*)(dstb + (size_t)r0 * 768 + cl)       = o0;
                *(float2*)(dstb + (size_t)(r0 + 8) * 768 + cl) = o1;
            }
        }
    } else {
        const int gcb = n0 + wn * 64;
        #pragma unroll
        for (int t = 0; t < 2; t++) {
            int r0 = m0 + wm * 32 + t * 16 + (lane >> 2);
            #pragma unroll
            for (int nt = 0; nt < 8; nt++) {
                int gc = gcb + nt * 8 + (lane & 3) * 2;
                float2 bv = *(const float2*)(b0 + gc);
                float2 o0, o1;
                o0.x = fmaxf(acc[t][nt][0] + bv.x, 0.f);
                o0.y = fmaxf(acc[t][nt][1] + bv.y, 0.f);
                o1.x = fmaxf(acc[t][nt][2] + bv.x, 0.f);
                o1.y = fmaxf(acc[t][nt][3] + bv.y, 0.f);
                *(float2*)(g_z + (size_t)r0 * 768 + gc)       = o0;
                *(float2*)(g_z + (size_t)(r0 + 8) * 768 + gc) = o1;
            }
        }
    }
}

// ===========================================================================
// K2: qk_hmma — S = Q·K^T + bias, 96 batches, tile 128x128, K=64.
// ===========================================================================
#define QK_SMEM 65536
__global__ __launch_bounds__(256, 2) void qk_hmma(const float* __restrict__ bias)
{
    extern __shared__ char smem[];
    const int tid = threadIdx.x, wid = tid >> 5, lane = tid & 31;
    const int q0 = blockIdx.x * 128, k0 = blockIdx.y * 128;
    const int bh = blockIdx.z, b = bh / 12, h = bh % 12;
    const int wm = wid & 3, wn = wid >> 2;
    const uint32_t a_hi = smem_u32(smem);
    const uint32_t a_lo = a_hi + 16384, b_hi = a_hi + 32768, b_lo = a_hi + 49152;

    const float* Qb = g_q + (size_t)(b * 256 + q0) * 768 + h * 64;
    const float* Kb = g_k + (size_t)(b * 256 + k0) * 768 + h * 64;
    #pragma unroll
    for (int i = 0; i < 8; i++) {
        int fid = i * 256 + tid;
        int row = fid >> 4, c4 = fid & 15;
        uint32_t off = SMEM_SWZ((uint32_t)(row * 128 + c4 * 8));
        uint2 hi, lo;
        cvt_hilo(*(const float4*)(Qb + (size_t)row * 768 + c4 * 4), hi, lo);
        *(uint2*)(smem + off)         = hi;
        *(uint2*)(smem + 16384 + off) = lo;
        cvt_hilo(*(const float4*)(Kb + (size_t)row * 768 + c4 * 4), hi, lo);
        *(uint2*)(smem + 32768 + off) = hi;
        *(uint2*)(smem + 49152 + off) = lo;
    }
    __syncthreads();

    float acc[2][8][4];
    #pragma unroll
    for (int t = 0; t < 2; t++)
        #pragma unroll
        for (int n = 0; n < 8; n++)
            #pragma unroll
            for (int j = 0; j < 4; j++) acc[t][n][j] = 0.f;

    const int arow = wm * 32 + (lane & 15);
    const int brow = wn * 64 + (lane & 15);
    const int cbyt = (lane >> 4) * 16;
    #pragma unroll
    for (int ks = 0; ks < 4; ks++) {
        const int kb = ks * 32 + cbyt;
        uint32_t ah[2][4], al[2][4];
        #pragma unroll
        for (int t = 0; t < 2; t++) {
            uint32_t off = SMEM_SWZ((uint32_t)((arow + t * 16) * 128 + kb));
            LDSM4(ah[t], a_hi + off);
            LDSM4(al[t], a_lo + off);
        }
        uint32_t bhf[4][4], blf[4][4];
        #pragma unroll
        for (int g = 0; g < 4; g++) {
            uint32_t off = SMEM_SWZ((uint32_t)((brow + g * 16) * 128 + kb));
            LDSM4(bhf[g], b_hi + off);
            LDSM4(blf[g], b_lo + off);
        }
        #pragma unroll
        for (int t = 0; t < 2; t++)
            #pragma unroll
            for (int g = 0; g < 4; g++) {
                MMA16816(acc[t][2 * g + 0], ah[t], bhf[g][0], bhf[g][2]);
                MMA16816(acc[t][2 * g + 1], ah[t], bhf[g][1], bhf[g][3]);
                MMA16816(acc[t][2 * g + 0], ah[t], blf[g][0], blf[g][2]);
                MMA16816(acc[t][2 * g + 1], ah[t], blf[g][1], blf[g][3]);
                MMA16816(acc[t][2 * g + 0], al[t], bhf[g][0], bhf[g][2]);
                MMA16816(acc[t][2 * g + 1], al[t], bhf[g][1], bhf[g][3]);
            }
    }

    const size_t rbase = (size_t)bh * 256;
    #pragma unroll
    for (int t = 0; t < 2; t++) {
        int r0 = q0 + wm * 32 + t * 16 + (lane >> 2);
        #pragma unroll
        for (int nt = 0; nt < 8; nt++) {
            int cl = k0 + wn * 64 + nt * 8 + (lane & 3) * 2;
            size_t i0 = (rbase + r0) * 256 + cl;
            size_t i1 = (rbase + r0 + 8) * 256 + cl;
            float2 bv0 = *(const float2*)(bias + i0);
            float2 bv1 = *(const float2*)(bias + i1);
            float2 o0, o1;
            o0.x = acc[t][nt][0] + bv0.x;
            o0.y = acc[t][nt][1] + bv0.y;
            o1.x = acc[t][nt][2] + bv1.x;
            o1.y = acc[t][nt][3] + bv1.y;
            *(float2*)(g_sw + i0) = o0;
            *(float2*)(g_sw + i1) = o1;
        }
    }
}

// ===========================================================================
// K3: qw_hmma — qw[bq, h*128+p] = q[bq,h,:]·Wsk[p,:], fp16 out. grid (16,12).
// ===========================================================================
__global__ __launch_bounds__(256, 2) void qw_hmma(const float* __restrict__ Wsk)
{
    extern __shared__ char smem[];
    const int tid = threadIdx.x, wid = tid >> 5, lane = tid & 31;
    const int m0 = blockIdx.x * 128;
    const int h  = blockIdx.y;
    const int wm = wid & 3, wn = wid >> 2;
    const uint32_t a_hi = smem_u32(smem);
    const uint32_t a_lo = a_hi + 16384, b_hi = a_hi + 32768, b_lo = a_hi + 49152;

    #pragma unroll
    for (int i = 0; i < 8; i++) {
        int fid = i * 256 + tid;
        int row = fid >> 4, c4 = fid & 15;
        uint32_t off = SMEM_SWZ((uint32_t)(row * 128 + c4 * 8));
        uint2 hi, lo;
        cvt_hilo(*(const float4*)(g_q + (size_t)(m0 + row) * 768 + h * 64 + c4 * 4), hi, lo);
        *(uint2*)(smem + off)         = hi;
        *(uint2*)(smem + 16384 + off) = lo;
        cvt_hilo(*(const float4*)(Wsk + row * 64 + c4 * 4), hi, lo);
        *(uint2*)(smem + 32768 + off) = hi;
        *(uint2*)(smem + 49152 + off) = lo;
    }
    __syncthreads();

    float acc[2][8][4];
    #pragma unroll
    for (int t = 0; t < 2; t++)
        #pragma unroll
        for (int n = 0; n < 8; n++)
            #pragma unroll
            for (int j = 0; j < 4; j++) acc[t][n][j] = 0.f;

    const int arow = wm * 32 + (lane & 15);
    const int brow = wn * 64 + (lane & 15);
    const int cbyt = (lane >> 4) * 16;
    #pragma unroll
    for (int ks = 0; ks < 4; ks++) {
        const int kb = ks * 32 + cbyt;
        uint32_t ah[2][4], al[2][4];
        #pragma unroll
        for (int t = 0; t < 2; t++) {
            uint32_t off = SMEM_SWZ((uint32_t)((arow + t * 16) * 128 + kb));
            LDSM4(ah[t], a_hi + off);
            LDSM4(al[t], a_lo + off);
        }
        uint32_t bhf[4][4], blf[4][4];
        #pragma unroll
        for (int g = 0; g < 4; g++) {
            uint32_t off = SMEM_SWZ((uint32_t)((brow + g * 16) * 128 + kb));
            LDSM4(bhf[g], b_hi + off);
            LDSM4(blf[g], b_lo + off);
        }
        #pragma unroll
        for (int t = 0; t < 2; t++)
            #pragma unroll
            for (int g = 0; g < 4; g++) {
                MMA16816(acc[t][2 * g + 0], ah[t], bhf[g][0], bhf[g][2]);
                MMA16816(acc[t][2 * g + 1], ah[t], bhf[g][1], bhf[g][3]);
                MMA16816(acc[t][2 * g + 0], ah[t], blf[g][0], blf[g][2]);
                MMA16816(acc[t][2 * g + 1], ah[t], blf[g][1], blf[g][3]);
                MMA16816(acc[t][2 * g + 0], al[t], bhf[g][0], bhf[g][2]);
                MMA16816(acc[t][2 * g + 1], al[t], bhf[g][1], bhf[g][3]);
            }
    }

    #pragma unroll
    for (int t = 0; t < 2; t++) {
        int r0 = m0 + wm * 32 + t * 16 + (lane >> 2);
        #pragma unroll
        for (int nt = 0; nt < 8; nt++) {
            int cl = h * 128 + wn * 64 + nt * 8 + (lane & 3) * 2;
            *(__half2*)(g_qwh + (size_t)r0 * 1536 + cl) =
                __floats2half2_rn(acc[t][nt][0], acc[t][nt][1]);
            *(__half2*)(g_qwh + (size_t)(r0 + 8) * 1536 + cl) =
                __floats2half2_rn(acc[t][nt][2], acc[t][nt][3]);
        }
    }
}

// ===========================================================================
// K4: attn_struct — per (b,q) CTA; cp.async LN + g_sw prefetch; qc computed
// in-prologue (warps 0..11); HMMA phases C, E, F (F on warps 0..7).
// ===========================================================================
#define PN_STR 136
#define QW_STR 136
#define WH_STR 264
#define WSV_STR 136
#define STG_STR 132
#define OFF_QWH 69632
#define OFF_WH  73984
#define OFF_SS  82432
#define OFF_QCV 94720
#define OFF_STG 94784
#define AT_SMEM 112192   // 94784 + max(16896 stage, 17408 WsvT)
__global__ __launch_bounds__(512, 2) void attn_struct_kernel(
    const float* __restrict__ paths,
    const float* __restrict__ Wsv, const float* __restrict__ bsv,
    const float* __restrict__ gpath, const float* __restrict__ bpath,
    const float* __restrict__ bsk)
{
    extern __shared__ char smraw[];
    __half* pn   = (__half*)smraw;
    __half* qwh  = (__half*)(smraw + OFF_QWH);    // A for C; wp fp16 for F
    __half* wh   = (__half*)(smraw + OFF_WH);
    float*  ss   = (float*)(smraw + OFF_SS);
    float*  qcv  = (float*)(smraw + OFF_QCV);
    float*  stage = (float*)(smraw + OFF_STG);
    __half* wsvT = (__half*)(smraw + OFF_STG);    // [64 d][136 p] after Phase A
    const uint32_t pn_u   = smem_u32(pn);
    const uint32_t qwh_u  = smem_u32(qwh);
    const uint32_t wh_u   = smem_u32(wh);
    const uint32_t stg_u  = smem_u32(stage);
    const uint32_t ss_u   = smem_u32(ss);
    const uint32_t wsvT_u = stg_u;

    const int b  = blockIdx.y;
    const int qi = blockIdx.x;
    const int bq = b * 256 + qi;
    const int tid  = threadIdx.x;
    const int warp = tid >> 5;
    const int lane = tid & 31;

    // ---- prologue: chunk0 cp.async + g_sw prefetch into ss (group 0) ----
    const float* prow = paths + (size_t)bq * 32768;
    const uint32_t doff = (uint32_t)(warp * STG_STR + lane * 4) * 4;
    {
        CP_ASYNC16(stg_u + doff, prow + (size_t)warp * 128 + lane * 4);
        const float* swsrc = g_sw + ((size_t)(b * 12) * 256 + qi) * 256;
        {
            int idx = tid;
            int hh = idx >> 6, k4 = idx & 63;
            CP_ASYNC16(ss_u + (uint32_t)(hh * 256 + k4 * 4) * 4,
                       swsrc + (size_t)hh * 65536 + k4 * 4);
        }
        if (tid < 256) {
            int idx = 512 + tid;
            int hh = idx >> 6, k4 = idx & 63;
            CP_ASYNC16(ss_u + (uint32_t)(hh * 256 + k4 * 4) * 4,
                       swsrc + (size_t)hh * 65536 + k4 * 4);
        }
        CP_COMMIT();
        CP_ASYNC16(stg_u + 16 * STG_STR * 4 + doff,
                   prow + (size_t)(16 + warp) * 128 + lane * 4);
        CP_COMMIT();
    }

    // ---- qc in-place: warp h computes qcv[h] = q[bq,h,:].bsk (fp32) ----
    if (warp < 12) {
        const float* qrow = g_q + (size_t)bq * 768 + warp * 64;
        float a = qrow[lane] * bsk[lane] + qrow[lane + 32] * bsk[lane + 32];
        #pragma unroll
        for (int o = 16; o > 0; o >>= 1)
            a += __shfl_xor_sync(0xffffffffu, a, o);
        if (lane == 0) qcv[warp] = a;
    }

    // ---- init: qwh from g_qwh, zero pads ----
    if (tid < 192) {
        uint4 v = *(const uint4*)(g_qwh + (size_t)bq * 1536 + tid * 8);
        int h = (tid * 8) >> 7, p = (tid * 8) & 127;
        *(uint4*)(qwh + h * QW_STR + p) = v;
    } else {
        int t = tid - 192;
        __half2 z = __half2half2(__float2half(0.f));
        if (t < 272) *((__half2*)(qwh + 12 * QW_STR) + t) = z;
        #pragma unroll
        for (int i = 0; i < 2; i++) {
            int o = t + i * 320;
            if (o < 528) *((__half2*)(wh + 12 * WH_STR) + o) = z;
        }
    }

    // ---- Phase A: cp.async-pipelined LN (16-row chunks, depth 2) ----
    {
        float4 gp = *(const float4*)(gpath + lane * 4);
        float4 bp = *(const float4*)(bpath + lane * 4);
        for (int c = 0; c < 16; c++) {
            if (c < 15) { CP_WAIT(1); } else { CP_WAIT(0); }
            const float* sp = stage + (c & 1) * (16 * STG_STR) +
                              warp * STG_STR + lane * 4;
            float4 xv = *(const float4*)sp;
            if (c < 14) {
                CP_ASYNC16(stg_u + (c & 1) * (16 * STG_STR * 4) + doff,
                           prow + (size_t)((c + 2) * 16 + warp) * 128 + lane * 4);
                CP_COMMIT();
            }
            float s  = xv.x + xv.y + xv.z + xv.w;
            float sq = xv.x * xv.x + xv.y * xv.y + xv.z * xv.z + xv.w * xv.w;
            #pragma unroll
            for (int o = 16; o > 0; o >>= 1) {
                s  += __shfl_xor_sync(0xffffffffu, s,  o);
                sq += __shfl_xor_sync(0xffffffffu, sq, o);
            }
            float mu  = s * 0.0078125f;
            float var = sq * 0.0078125f - mu * mu;
            float rs  = rsqrtf(var + EPS);
            float y0 = (xv.x - mu) * rs * gp.x + bp.x;
            float y1 = (xv.y - mu) * rs * gp.y + bp.y;
            float y2 = (xv.z - mu) * rs * gp.z + bp.z;
            float y3 = (xv.w - mu) * rs * gp.w + bp.w;
            __half* pr = pn + (c * 16 + warp) * PN_STR + lane * 4;
            *(__half2*)(pr)     = __floats2half2_rn(y0, y1);
            *(__half2*)(pr + 2) = __floats2half2_rn(y2, y3);
        }
    }
    __syncthreads();

    // ---- stage WsvT fp16 into (now dead) stage region: wsvT[d][p] ----
    #pragma unroll
    for (int i = 0; i < 16; i++) {
        int idx = i * 512 + tid;
        int p = idx >> 6, d = idx & 63;
        wsvT[d * WSV_STR + p] = __float2half(Wsv[idx]);
    }

    // ---- Phase C (HMMA): ss[h][key] = qw·pn + qc + prefetched content ----
    {
        const int n0 = warp * 16;
        const uint32_t aaddr = qwh_u + ((lane & 15) * QW_STR + (lane >> 4) * 8) * 2;
        const uint32_t baddr = pn_u + ((n0 + (lane & 15)) * PN_STR + (lane >> 4) * 8) * 2;
        float c0[4] = {0.f, 0.f, 0.f, 0.f};
        float c1[4] = {0.f, 0.f, 0.f, 0.f};
        #pragma unroll
        for (int kc = 0; kc < 8; kc++) {
            uint32_t a[4], bm[4];
            LDSM4(a, aaddr + kc * 32);
            LDSM4(bm, baddr + kc * 32);
            MMA16816H(c0, a, bm[0], bm[2]);
            MMA16816H(c1, a, bm[1], bm[3]);
        }
        const int h0 = lane >> 2;
        const int kk = (lane & 3) * 2;
        {
            float qc0 = qcv[h0];
            float* r = ss + h0 * 256 + n0;
            r[kk]     = c0[0] + qc0 + r[kk];
            r[kk + 1] = c0[1] + qc0 + r[kk + 1];
            r[8 + kk]     = c1[0] + qc0 + r[8 + kk];
            r[8 + kk + 1] = c1[1] + qc0 + r[8 + kk + 1];
        }
        if (h0 < 4) {
            const int h1 = h0 + 8;
            float qc1 = qcv[h1];
            float* r = ss + h1 * 256 + n0;
            r[kk]     = c0[2] + qc1 + r[kk];
            r[kk + 1] = c0[3] + qc1 + r[kk + 1];
            r[8 + kk]     = c1[2] + qc1 + r[8 + kk];
            r[8 + kk + 1] = c1[3] + qc1 + r[8 + kk + 1];
        }
    }
    __syncthreads();

    // ---- Phase D: softmax; fp16 weights -> g_swh and wh ----
    if (warp < 12) {
        float* row = ss + warp * 256;
        float vals[8], m = -1e30f;
        #pragma unroll
        for (int i = 0; i < 8; i++) {
            vals[i] = row[lane + i * 32];
            m = fmaxf(m, vals[i]);
        }
        #pragma unroll
        for (int o = 16; o > 0; o >>= 1)
            m = fmaxf(m, __shfl_xor_sync(0xffffffffu, m, o));
        float s = 0.f;
        #pragma unroll
        for (int i = 0; i < 8; i++) { vals[i] = __expf(vals[i] - m); s += vals[i]; }
        #pragma unroll
        for (int o = 16; o > 0; o >>= 1)
            s += __shfl_xor_sync(0xffffffffu, s, o);
        float inv = 1.f / s;
        __half* gwh = g_swh + ((size_t)(b * 12 + warp) * 256 + qi) * 256;
        __half* whr = wh + warp * WH_STR;
        #pragma unroll
        for (int i = 0; i < 8; i++) {
            __half w = __float2half_rn(vals[i] * inv);
            gwh[lane + i * 32] = w;
            whr[lane + i * 32] = w;
        }
    }
    __syncthreads();

    // ---- Phase E (HMMA): wp[h][p] = Σ_k w[h,k]·pn[k,p] -> qwh (fp16) ----
    {
        const int p0 = warp * 8;
        const uint32_t aaddr = wh_u + ((lane & 15) * WH_STR + (lane >> 4) * 8) * 2;
        const uint32_t baddr = pn_u + ((lane & 15) * PN_STR + p0) * 2;
        float c[4] = {0.f, 0.f, 0.f, 0.f};
        #pragma unroll
        for (int kc = 0; kc < 16; kc++) {
            uint32_t a[4], bm[2];
            LDSM4(a, aaddr + kc * 32);
            LDSM2T(bm, baddr + kc * 16 * PN_STR * 2);
            MMA16816H(c, a, bm[0], bm[1]);
        }
        const int h0 = lane >> 2;
        const int pp = p0 + (lane & 3) * 2;
        *(__half2*)(qwh + h0 * QW_STR + pp) = __floats2half2_rn(c[0], c[1]);
        if (h0 < 4)
            *(__half2*)(qwh + (h0 + 8) * QW_STR + pp) = __floats2half2_rn(c[2], c[3]);
    }
    __syncthreads();

    // ---- Phase F (HMMA, warps 0..7): out[h,d] = Σ_p wp[h,p]·Wsv[p,d]+bsv ----
    if (warp < 8) {
        const int n0 = warp * 8;
        const uint32_t aaddr = qwh_u + ((lane & 15) * QW_STR + (lane >> 4) * 8) * 2;
        const uint32_t baddr = wsvT_u + ((n0 + (lane & 7)) * WSV_STR +
                                         ((lane >> 3) & 1) * 8) * 2;
        float c[4] = {0.f, 0.f, 0.f, 0.f};
        #pragma unroll
        for (int kc = 0; kc < 8; kc++) {
            uint32_t a[4], bm[2];
            LDSM4(a, aaddr + kc * 32);
            LDSM2(bm, baddr + kc * 32);
            MMA16816H(c, a, bm[0], bm[1]);
        }
        float* aout = g_attn + (size_t)bq * 768;
        const int h0 = lane >> 2;
        const int dd = n0 + (lane & 3) * 2;
        float2 bv = *(const float2*)(bsv + dd);
        float2 o0;
        o0.x = c[0] + bv.x;
        o0.y = c[1] + bv.y;
        *(float2*)(aout + h0 * 64 + dd) = o0;
        if (h0 < 4) {
            float2 o1;
            o1.x = c[2] + bv.x;
            o1.y = c[3] + bv.y;
            *(float2*)(aout + (h0 + 8) * 64 + dd) = o1;
        }
    }
}

// ===========================================================================
// K5: wv_hmma — g_attn += W(fp16) @ V(hi/lo fp16). grid (2, 96). 2 CTAs/SM.
// ===========================================================================
#define WV_SMEM 34816
#define V_STR 72
__global__ __launch_bounds__(256, 2) void wv_hmma()
{
    extern __shared__ char smem[];
    const int tid = threadIdx.x, wid = tid >> 5, lane = tid & 31;
    const int q0 = blockIdx.x * 128;
    const int bh = blockIdx.y, b = bh / 12, h = bh % 12;
    const int wm = wid & 3, wn = wid >> 2;
    const uint32_t w_u = smem_u32(smem);
    const uint32_t vh_u = w_u + 16384;
    const uint32_t vl_u = w_u + 16384 + 9216;

    float acc[2][4][4];
    #pragma unroll
    for (int t = 0; t < 2; t++)
        #pragma unroll
        for (int g = 0; g < 4; g++)
            #pragma unroll
            for (int j = 0; j < 4; j++) acc[t][g][j] = 0.f;

    const __half* Wb = g_swh + ((size_t)bh * 256 + q0) * 256;
    const float* Vb = g_v + (size_t)(b * 256) * 768 + h * 64;

    for (int kc = 0; kc < 4; kc++) {
        #pragma unroll
        for (int i = 0; i < 4; i++) {
            int fid = i * 256 + tid;
            int row = fid >> 3, c8 = fid & 7;
            uint4 v = *(const uint4*)(Wb + (size_t)row * 256 + kc * 64 + c8 * 8);
            *(uint4*)(smem + SMEM_SWZ((uint32_t)(row * 128 + c8 * 16))) = v;
        }
        #pragma unroll
        for (int i = 0; i < 4; i++) {
            int fid = i * 256 + tid;
            int row = fid >> 4, c4 = fid & 15;
            float4 v = *(const float4*)(Vb + (size_t)(kc * 64 + row) * 768 + c4 * 4);
            __half h0 = __float2half(v.x), h1 = __float2half(v.y);
            __half h2 = __float2half(v.z), h3 = __float2half(v.w);
            __half l0 = __float2half(v.x - __half2float(h0));
            __half l1 = __float2half(v.y - __half2float(h1));
            __half l2 = __float2half(v.z - __half2float(h2));
            __half l3 = __float2half(v.w - __half2float(h3));
            uint32_t off = (uint32_t)(row * V_STR + c4 * 4) * 2;
            *(uint2*)(smem + 16384 + off)        = make_uint2(pack2h(h0, h1), pack2h(h2, h3));
            *(uint2*)(smem + 16384 + 9216 + off) = make_uint2(pack2h(l0, l1), pack2h(l2, l3));
        }
        __syncthreads();

        #pragma unroll
        for (int ks = 0; ks < 4; ks++) {
            uint32_t a[2][4];
            #pragma unroll
            for (int t = 0; t < 2; t++) {
                uint32_t off = SMEM_SWZ((uint32_t)((wm * 32 + (lane & 15) + t * 16) * 128 +
                                                   ks * 32 + (lane >> 4) * 16));
                LDSM4(a[t], w_u + off);
            }
            #pragma unroll
            for (int g = 0; g < 4; g++) {
                uint32_t boff = (uint32_t)((ks * 16 + (lane & 15)) * V_STR +
                                           wn * 32 + g * 8) * 2;
                uint32_t bhv[2], blv[2];
                LDSM2T(bhv, vh_u + boff);
                LDSM2T(blv, vl_u + boff);
                #pragma unroll
                for (int t = 0; t < 2; t++) {
                    MMA16816H(acc[t][g], a[t], bhv[0], bhv[1]);
                    MMA16816H(acc[t][g], a[t], blv[0], blv[1]);
                }
            }
        }
        __syncthreads();
    }

    #pragma unroll
    for (int t = 0; t < 2; t++) {
        int r0 = q0 + wm * 32 + t * 16 + (lane >> 2);
        #pragma unroll
        for (int g = 0; g < 4; g++) {
            int col = h * 64 + wn * 32 + g * 8 + (lane & 3) * 2;
            float* d0 = g_attn + ((size_t)(b * 256) + r0) * 768 + col;
            float* d1 = d0 + 8 * 768;
            float2 o0 = *(float2*)d0, o1 = *(float2*)d1;
            o0.x += acc[t][g][0]; o0.y += acc[t][g][1];
            o1.x += acc[t][g][2]; o1.y += acc[t][g][3];
            *(float2*)d0 = o0;
            *(float2*)d1 = o1;
        }
    }
}

// ===========================================================================
// K8: out = LN(nodes + g_z). One warp per row.
// ===========================================================================
__global__ __launch_bounds__(256) void final_ln(
    const float* __restrict__ nodes,
    const float* __restrict__ gout, const float* __restrict__ bout,
    float* __restrict__ out)
{
    const int row  = blockIdx.x * 8 + (threadIdx.x >> 5);
    const int lane = threadIdx.x & 31;
    const float* x1 = nodes + (size_t)row * 768;
    const float* x2 = g_z   + (size_t)row * 768;

    float v[24];
    float s = 0.f, sq = 0.f;
    #pragma unroll
    for (int i = 0; i < 6; i++) {
        float4 a = *(const float4*)(x1 + i * 128 + lane * 4);
        float4 c = *(const float4*)(x2 + i * 128 + lane * 4);
        float t0 = a.x + c.x, t1 = a.y + c.y, t2 = a.z + c.z, t3 = a.w + c.w;
        v[i * 4 + 0] = t0; v[i * 4 + 1] = t1; v[i * 4 + 2] = t2; v[i * 4 + 3] = t3;
        s += t0 + t1 + t2 + t3;
        sq += t0 * t0 + t1 * t1 + t2 * t2 + t3 * t3;
    }
    #pragma unroll
    for (int o = 16; o > 0; o >>= 1) {
        s  += __shfl_xor_sync(0xffffffffu, s,  o);
        sq += __shfl_xor_sync(0xffffffffu, sq, o);
    }
    const float inv = 1.f / 768.f;
    float mu  = s * inv;
    float var = sq * inv - mu * mu;
    float rs  = rsqrtf(var + EPS);

    float* orow = out + (size_t)row * 768;
    #pragma unroll
    for (int i = 0; i < 6; i++) {
        int idx = i * 128 + lane * 4;
        float4 g4 = *(const float4*)(gout + idx);
        float4 b4 = *(const float4*)(bout + idx);
        float4 r;
        r.x = (v[i * 4 + 0] - mu) * rs * g4.x + b4.x;
        r.y = (v[i * 4 + 1] - mu) * rs * g4.y + b4.y;
        r.z = (v[i * 4 + 2] - mu) * rs * g4.z + b4.z;
        r.w = (v[i * 4 + 3] - mu) * rs * g4.w + b4.w;
        *(float4*)(orow + idx) = r;
    }
}

// ===========================================================================
extern "C" void kernel_launch(void* const* d_in, const int* in_sizes, int n_in,
                              void* d_out, int out_size)
{
    const float* nodes = (const float*)d_in[0];
    const float* bias  = (const float*)d_in[1];
    const float* paths = (const float*)d_in[2];
    const float* Wq  = (const float*)d_in[3];
    const float* bq  = (const float*)d_in[4];
    const float* Wk  = (const float*)d_in[5];
    const float* bk  = (const float*)d_in[6];
    const float* Wv  = (const float*)d_in[7];
    const float* bv  = (const float*)d_in[8];
    const float* Wsk = (const float*)d_in[9];
    const float* bsk = (const float*)d_in[10];
    const float* Wsv = (const float*)d_in[11];
    const float* bsv = (const float*)d_in[12];
    const float* Wo  = (const float*)d_in[13];
    const float* bo  = (const float*)d_in[14];
    const float* gpath = (const float*)d_in[15];
    const float* bpath = (const float*)d_in[16];
    const float* gout  = (const float*)d_in[17];
    const float* bout  = (const float*)d_in[18];
    float* out = (float*)d_out;

    static cudaStream_t s2;
    static cudaEvent_t ev_fork, ev_act, ev_fork2, ev_join;
    static bool init_done = false;
    if (!init_done) {
        cudaFuncSetAttribute(attn_struct_kernel,
                             cudaFuncAttributeMaxDynamicSharedMemorySize, AT_SMEM);
        cudaFuncSetAttribute(hmma_gemm,
                             cudaFuncAttributeMaxDynamicSharedMemorySize, HG_SMEM);
        cudaFuncSetAttribute(qk_hmma,
                             cudaFuncAttributeMaxDynamicSharedMemorySize, QK_SMEM);
        cudaFuncSetAttribute(qw_hmma,
                             cudaFuncAttributeMaxDynamicSharedMemorySize, QK_SMEM);
        cudaStreamCreateWithFlags(&s2, cudaStreamNonBlocking);
        cudaEventCreateWithFlags(&ev_fork, cudaEventDisableTiming);
        cudaEventCreateWithFlags(&ev_act, cudaEventDisableTiming);
        cudaEventCreateWithFlags(&ev_fork2, cudaEventDisableTiming);
        cudaEventCreateWithFlags(&ev_join, cudaEventDisableTiming);
        init_done = true;
    }

    float* fa_global;
    cudaGetSymbolAddress((void**)&fa_global, g_attn);

    // fork: prep_act(nodes) on s2 runs concurrently with prep_weights
    cudaEventRecord(ev_fork, 0);
    cudaStreamWaitEvent(s2, ev_fork, 0);
    prep_act<<<768, 256, 0, s2>>>(nodes);
    cudaEventRecord(ev_act, s2);

    prep_weights<<<dim3(48, 12), 256>>>(Wq, Wk, Wv, Wo);
    cudaStreamWaitEvent(0, ev_act, 0);

    hmma_gemm<<<dim3(18, 16), 256, HG_SMEM>>>(0, bq, bk, bv, 0);

    // fork: qw on s2 runs concurrently with qk on the default stream
    cudaEventRecord(ev_fork2, 0);
    cudaStreamWaitEvent(s2, ev_fork2, 0);
    qw_hmma<<<dim3(16, 12), 256, QK_SMEM, s2>>>(Wsk);
    qk_hmma<<<dim3(2, 2, 96), 256, QK_SMEM>>>(bias);
    cudaEventRecord(ev_join, s2);
    cudaStreamWaitEvent(0, ev_join, 0);

    attn_struct_kernel<<<dim3(256, 8), 512, AT_SMEM>>>(
        paths, Wsv, bsv, gpath, bpath, bsk);
    wv_hmma<<<dim3(2, 96), 256, WV_SMEM>>>();
    prep_act<<<768, 256>>>(fa_global);
    hmma_gemm<<<dim3(6, 16), 256, HG_SMEM>>>(2304, bo, bo, bo, 1);
    final_ln<<<256, 256>>>(nodes, gout, bout, out);
}